// round 1
// baseline (speedup 1.0000x reference)
#include <cuda_runtime.h>

#define N_USERS 100000
#define N_ITEMS 50000
#define NN      150000
#define NE      2000000
#define DD      64
#define NB      16384

// ---------------- scratch (device globals; no runtime allocation) ----------
__device__ float    g_x  [NN*DD];   // node features (input / layer outputs)
__device__ float    g_h  [NN*DD];   // x @ W
__device__ float    g_agg[NN*DD];   // unnormalized weighted sums
__device__ float    g_as [NN*4];
__device__ float    g_ad [NN*4];
__device__ unsigned g_m  [NN*4];    // encoded segment max
__device__ float    g_den[NN*4];
__device__ int      g_src[NE];
__device__ int      g_dst[NE];
__device__ int      g_is64;

// ---------------- helpers ---------------------------------------------------
__device__ __forceinline__ unsigned fenc(float f) {
    unsigned u = __float_as_uint(f);
    return (u & 0x80000000u) ? ~u : (u | 0x80000000u);
}
__device__ __forceinline__ float fdec(unsigned u) {
    return (u & 0x80000000u) ? __uint_as_float(u ^ 0x80000000u)
                             : __uint_as_float(~u);
}
__device__ __forceinline__ float lrelu(float x) { return x > 0.f ? x : 0.2f * x; }
__device__ __forceinline__ float eluf (float v) { return v > 0.f ? v : expf(v) - 1.f; }

// ---------------- kernels ----------------------------------------------------

// Detect whether the index buffers are int64 (x64 enabled) or int32.
// Node ids < 150000 << 2^31, so if int64 every odd int32 word is 0.
__global__ void k_detect(const int* __restrict__ ei) {
    if (threadIdx.x == 0) {
        int all0 = 1;
        for (int k = 0; k < 64; k++)
            if (ei[2 * k + 1] != 0) { all0 = 0; break; }
        g_is64 = all0;
    }
}

__global__ void k_edges(const void* __restrict__ ei) {
    int e = blockIdx.x * blockDim.x + threadIdx.x;
    if (e >= NE) return;
    if (g_is64) {
        const long long* p = (const long long*)ei;
        g_src[e] = (int)p[e];
        g_dst[e] = (int)p[NE + e];
    } else {
        const int* p = (const int*)ei;
        g_src[e] = p[e];
        g_dst[e] = p[NE + e];
    }
}

__global__ void k_concat(const float* __restrict__ ue, const float* __restrict__ ie) {
    int i = blockIdx.x * blockDim.x + threadIdx.x;   // over NN*DD/4 float4s
    const int NU4 = N_USERS * DD / 4;
    const int NT4 = NN * DD / 4;
    if (i >= NT4) return;
    float4* X = (float4*)g_x;
    if (i < NU4) X[i] = ((const float4*)ue)[i];
    else         X[i] = ((const float4*)ie)[i - NU4];
}

// h = x @ W  (64x64 weight).  16 nodes per 256-thread block.
__global__ void k_gemm(const float* __restrict__ W) {
    __shared__ float sW[64 * 64];
    __shared__ float sx[16 * 64];
    int t = threadIdx.x;
#pragma unroll
    for (int i = 0; i < 16; i++) sW[t + 256 * i] = W[t + 256 * i];
    int n0 = blockIdx.x * 16;
    int r = t >> 4, c = (t & 15) * 4;
    if (n0 + r < NN)
        *(float4*)&sx[r * 64 + c] = *(const float4*)&g_x[(n0 + r) * 64 + c];
    __syncthreads();
    int ni = t >> 4, j0 = (t & 15) * 4;
    if (n0 + ni >= NN) return;
    float4 acc = make_float4(0.f, 0.f, 0.f, 0.f);
#pragma unroll
    for (int k = 0; k < 64; k++) {
        float  xv = sx[ni * 64 + k];
        float4 w  = *(float4*)&sW[k * 64 + j0];
        acc.x += xv * w.x; acc.y += xv * w.y;
        acc.z += xv * w.z; acc.w += xv * w.w;
    }
    *(float4*)&g_h[(n0 + ni) * 64 + j0] = acc;
}

// per (node, head): alpha_src, alpha_dst, and init segment-max with self-loop
template <int H, int F>
__global__ void k_alpha(const float* __restrict__ a_src, const float* __restrict__ a_dst) {
    int idx = blockIdx.x * blockDim.x + threadIdx.x;
    if (idx >= NN * H) return;
    int n = idx / H, h = idx - n * H;
    const float* hr = &g_h[n * 64 + h * F];
    float s = 0.f, d = 0.f;
#pragma unroll
    for (int f = 0; f < F; f++) {
        float v = hr[f];
        s += v * a_src[h * F + f];
        d += v * a_dst[h * F + f];
    }
    g_as[n * H + h] = s;
    g_ad[n * H + h] = d;
    g_m [n * H + h] = fenc(lrelu(s + d));   // self-loop seeds the max
}

// edge pass A: segment max
template <int H>
__global__ void k_emax() {
    int idx = blockIdx.x * blockDim.x + threadIdx.x;
    if (idx >= NE * H) return;
    int e = idx / H, h = idx - e * H;
    int s = g_src[e], d = g_dst[e];
    float v = lrelu(g_as[s * H + h] + g_ad[d * H + h]);
    atomicMax(&g_m[d * H + h], fenc(v));
}

// node init: self-loop contribution to denom and agg
template <int H, int F>
__global__ void k_init() {
    int idx = blockIdx.x * blockDim.x + threadIdx.x;
    if (idx >= NN * 16) return;
    int n = idx >> 4, q = idx & 15;
    int j0 = q * 4, h = j0 / F;
    float m = fdec(g_m[n * H + h]);
    float w = expf(lrelu(g_as[n * H + h] + g_ad[n * H + h]) - m);
    if ((j0 & (F - 1)) == 0) g_den[n * H + h] = w;
    float4 hv = *(const float4*)&g_h[n * 64 + j0];
    hv.x *= w; hv.y *= w; hv.z *= w; hv.w *= w;
    *(float4*)&g_agg[n * 64 + j0] = hv;
}

// edge pass B: 16 threads/edge, weighted scatter of h[src] into agg[dst]
template <int H, int F>
__global__ void k_eagg() {
    int idx = blockIdx.x * blockDim.x + threadIdx.x;
    if (idx >= NE * 16) return;
    int e = idx >> 4, q = idx & 15;
    int j0 = q * 4, h = j0 / F;
    int s = g_src[e], d = g_dst[e];
    float w = expf(lrelu(g_as[s * H + h] + g_ad[d * H + h]) - fdec(g_m[d * H + h]));
    if ((j0 & (F - 1)) == 0) atomicAdd(&g_den[d * H + h], w);
    float4 hv = *(const float4*)&g_h[s * 64 + j0];
    float* p = &g_agg[d * 64 + j0];
    asm volatile("red.global.add.v4.f32 [%0], {%1,%2,%3,%4};"
                 :: "l"(__cvta_generic_to_global(p)),
                    "f"(hv.x * w), "f"(hv.y * w), "f"(hv.z * w), "f"(hv.w * w)
                 : "memory");
}

// finalize: out = elu(agg/denom + b) -> g_x
template <int H, int F>
__global__ void k_fin(const float* __restrict__ b) {
    int idx = blockIdx.x * blockDim.x + threadIdx.x;
    if (idx >= NN * 16) return;
    int n = idx >> 4, q = idx & 15;
    int j0 = q * 4, h = j0 / F;
    float inv = 1.f / g_den[n * H + h];
    float4 a = *(const float4*)&g_agg[n * 64 + j0];
    float4 o;
    o.x = eluf(a.x * inv + b[j0 + 0]);
    o.y = eluf(a.y * inv + b[j0 + 1]);
    o.z = eluf(a.z * inv + b[j0 + 2]);
    o.w = eluf(a.w * inv + b[j0 + 3]);
    *(float4*)&g_x[n * 64 + j0] = o;
}

// final: gather pair, dot64, sigmoid.  8 threads per pair.
__global__ void k_score(const void* __restrict__ bu_, const void* __restrict__ bi_,
                        float* __restrict__ out) {
    int gid = blockIdx.x * blockDim.x + threadIdx.x;
    if (gid >= NB * 8) return;
    int p = gid >> 3, l = gid & 7;
    int u, it;
    if (g_is64) {
        u  = (int)((const long long*)bu_)[p];
        it = (int)((const long long*)bi_)[p];
    } else {
        u  = ((const int*)bu_)[p];
        it = ((const int*)bi_)[p];
    }
    const float* xu = &g_x[(long)u * 64];
    const float* xv = &g_x[((long)it + N_USERS) * 64];
    int o = l * 8;
    float acc = 0.f;
#pragma unroll
    for (int k = 0; k < 8; k++) acc += xu[o + k] * xv[o + k];
    acc += __shfl_xor_sync(0xffffffffu, acc, 1);
    acc += __shfl_xor_sync(0xffffffffu, acc, 2);
    acc += __shfl_xor_sync(0xffffffffu, acc, 4);
    if (l == 0) out[p] = 1.f / (1.f + expf(-acc));
}

// ---------------- host launcher ----------------------------------------------
extern "C" void kernel_launch(void* const* d_in, const int* in_sizes, int n_in,
                              void* d_out, int out_size) {
    const void *edge = nullptr, *bu = nullptr, *bi = nullptr;
    const float *ue = nullptr, *ie = nullptr, *W1 = nullptr, *W2 = nullptr;
    const float* v64[6] = {nullptr, nullptr, nullptr, nullptr, nullptr, nullptr};
    int c64 = 0;
    for (int i = 0; i < n_in; i++) {
        int sz = in_sizes[i];
        if      (sz == 2 * NE)        edge = d_in[i];
        else if (sz == NB)            { if (!bu) bu = d_in[i]; else bi = d_in[i]; }
        else if (sz == N_USERS * DD)  ue = (const float*)d_in[i];
        else if (sz == N_ITEMS * DD)  ie = (const float*)d_in[i];
        else if (sz == DD * DD)       { if (!W1) W1 = (const float*)d_in[i];
                                        else     W2 = (const float*)d_in[i]; }
        else if (sz == 64 && c64 < 6) v64[c64++] = (const float*)d_in[i];
    }
    const float *as1 = v64[0], *ad1 = v64[1], *b1 = v64[2];
    const float *as2 = v64[3], *ad2 = v64[4], *b2 = v64[5];

    const int TB = 256;
    k_detect<<<1, 32>>>((const int*)edge);
    k_edges <<<(NE + TB - 1) / TB, TB>>>(edge);
    k_concat<<<(NN * 16 + TB - 1) / TB, TB>>>(ue, ie);

    // ---- layer 1: H=4, F=16 ----
    k_gemm <<<(NN + 15) / 16, TB>>>(W1);
    k_alpha<4, 16><<<(NN * 4  + TB - 1) / TB, TB>>>(as1, ad1);
    k_emax <4>    <<<(NE * 4  + TB - 1) / TB, TB>>>();
    k_init <4, 16><<<(NN * 16 + TB - 1) / TB, TB>>>();
    k_eagg <4, 16><<<(NE * 16 + TB - 1) / TB, TB>>>();
    k_fin  <4, 16><<<(NN * 16 + TB - 1) / TB, TB>>>(b1);

    // ---- layer 2: H=1, F=64 ----
    k_gemm <<<(NN + 15) / 16, TB>>>(W2);
    k_alpha<1, 64><<<(NN      + TB - 1) / TB, TB>>>(as2, ad2);
    k_emax <1>    <<<(NE      + TB - 1) / TB, TB>>>();
    k_init <1, 64><<<(NN * 16 + TB - 1) / TB, TB>>>();
    k_eagg <1, 64><<<(NE * 16 + TB - 1) / TB, TB>>>();
    k_fin  <1, 64><<<(NN * 16 + TB - 1) / TB, TB>>>(b2);

    k_score<<<(NB * 8 + TB - 1) / TB, TB>>>(bu, bi, (float*)d_out);
}

// round 2
// speedup vs baseline: 1.5140x; 1.5140x over previous
#include <cuda_runtime.h>

#define N_USERS 100000
#define N_ITEMS 50000
#define NN      150000
#define NE      2000000
#define DD      64
#define NB      16384
#define SB      586      // ceil(NN/256) scan blocks

// ---------------- scratch (device globals) ----------------------------------
__device__ float g_x  [NN*DD];
__device__ float g_h  [NN*DD];
__device__ float g_as [NN*4];
__device__ float g_ad [NN*4];
__device__ int   g_src[NE];
__device__ int   g_dst[NE];
__device__ int   g_adj[NE];      // CSR adjacency (src per slot, grouped by dst)
__device__ int   g_cnt[NN];
__device__ int   g_off[NN+1];
__device__ int   g_pos[NN];
__device__ int   g_spine[1024];
__device__ int   g_is64;

// ---------------- helpers ---------------------------------------------------
__device__ __forceinline__ float lrelu(float x) { return x > 0.f ? x : 0.2f * x; }
__device__ __forceinline__ float eluf (float v) { return v > 0.f ? v : expf(v) - 1.f; }

// ---------------- index dtype detection -------------------------------------
__global__ void k_detect(const int* __restrict__ ei) {
    if (threadIdx.x == 0) {
        int all0 = 1;
        for (int k = 0; k < 64; k++)
            if (ei[2 * k + 1] != 0) { all0 = 0; break; }
        g_is64 = all0;
    }
}

// convert edges to int32 + zero the degree counters
__global__ void k_edges(const void* __restrict__ ei) {
    int e = blockIdx.x * blockDim.x + threadIdx.x;
    if (e < NN) g_cnt[e] = 0;
    if (e >= NE) return;
    if (g_is64) {
        const long long* p = (const long long*)ei;
        g_src[e] = (int)p[e];
        g_dst[e] = (int)p[NE + e];
    } else {
        const int* p = (const int*)ei;
        g_src[e] = p[e];
        g_dst[e] = p[NE + e];
    }
}

__global__ void k_concat(const float* __restrict__ ue, const float* __restrict__ ie) {
    int i = blockIdx.x * blockDim.x + threadIdx.x;
    const int NU4 = N_USERS * DD / 4;
    const int NT4 = NN * DD / 4;
    if (i >= NT4) return;
    float4* X = (float4*)g_x;
    if (i < NU4) X[i] = ((const float4*)ue)[i];
    else         X[i] = ((const float4*)ie)[i - NU4];
}

// ---------------- CSR build --------------------------------------------------
__global__ void k_count() {
    int e = blockIdx.x * blockDim.x + threadIdx.x;
    if (e >= NE) return;
    atomicAdd(&g_cnt[g_dst[e]], 1);
}

__global__ void k_s1() {                       // block sums -> spine
    __shared__ int sm[256];
    int i = blockIdx.x * 256 + threadIdx.x;
    sm[threadIdx.x] = (i < NN) ? g_cnt[i] : 0;
    __syncthreads();
    for (int s = 128; s > 0; s >>= 1) {
        if (threadIdx.x < s) sm[threadIdx.x] += sm[threadIdx.x + s];
        __syncthreads();
    }
    if (threadIdx.x == 0) g_spine[blockIdx.x] = sm[0];
}

__global__ void k_s2() {                       // exclusive scan of spine (1 block, 1024 thr)
    __shared__ int sm[1024];
    int t = threadIdx.x;
    sm[t] = (t < SB) ? g_spine[t] : 0;
    __syncthreads();
    for (int d = 1; d < 1024; d <<= 1) {
        int v = (t >= d) ? sm[t - d] : 0;
        __syncthreads();
        sm[t] += v;
        __syncthreads();
    }
    g_spine[t] = (t == 0) ? 0 : sm[t - 1];
    if (t == 0) g_off[NN] = NE;
}

__global__ void k_s3() {                       // per-block exclusive scan + spine offset
    __shared__ int sm[256];
    int t = threadIdx.x;
    int i = blockIdx.x * 256 + t;
    int v = (i < NN) ? g_cnt[i] : 0;
    sm[t] = v;
    __syncthreads();
    for (int d = 1; d < 256; d <<= 1) {
        int u = (t >= d) ? sm[t - d] : 0;
        __syncthreads();
        sm[t] += u;
        __syncthreads();
    }
    int excl = sm[t] - v + g_spine[blockIdx.x];
    if (i < NN) { g_off[i] = excl; g_pos[i] = excl; }
}

__global__ void k_scatter() {
    int e = blockIdx.x * blockDim.x + threadIdx.x;
    if (e >= NE) return;
    int d = g_dst[e];
    int p = atomicAdd(&g_pos[d], 1);
    g_adj[p] = g_src[e];
}

// ---------------- GEMM: h = x @ W  (W broadcast, x transposed in smem) -------
// 128 threads, 32 nodes/block. Warp w computes cols [16w,16w+16) for 32 nodes.
__global__ void k_gemm(const float* __restrict__ W) {
    __shared__ float sW[64 * 64];
    __shared__ float sx[64][33];
    int t = threadIdx.x;
#pragma unroll
    for (int i = 0; i < 8; i++)
        *(float4*)&sW[(t + 128 * i) * 4] = *(const float4*)&W[(t + 128 * i) * 4];
    int n0 = blockIdx.x * 32;
#pragma unroll
    for (int i = 0; i < 4; i++) {
        int f = t + 128 * i;            // float4 index in [0,512)
        int node = f >> 4;
        int col  = (f & 15) * 4;
        float4 v = make_float4(0.f, 0.f, 0.f, 0.f);
        if (n0 + node < NN) v = *(const float4*)&g_x[(n0 + node) * 64 + col];
        sx[col + 0][node] = v.x; sx[col + 1][node] = v.y;
        sx[col + 2][node] = v.z; sx[col + 3][node] = v.w;
    }
    __syncthreads();
    int w = t >> 5, lane = t & 31;
    int jc = w * 16;
    float acc[16];
#pragma unroll
    for (int i = 0; i < 16; i++) acc[i] = 0.f;
#pragma unroll 4
    for (int k = 0; k < 64; k++) {
        float xv = sx[k][lane];
#pragma unroll
        for (int q = 0; q < 4; q++) {
            float4 wv = *(float4*)&sW[k * 64 + jc + q * 4];
            acc[q * 4 + 0] += xv * wv.x;
            acc[q * 4 + 1] += xv * wv.y;
            acc[q * 4 + 2] += xv * wv.z;
            acc[q * 4 + 3] += xv * wv.w;
        }
    }
    int n = n0 + lane;
    if (n < NN) {
#pragma unroll
        for (int q = 0; q < 4; q++)
            *(float4*)&g_h[n * 64 + jc + q * 4] =
                make_float4(acc[q*4], acc[q*4+1], acc[q*4+2], acc[q*4+3]);
    }
}

// ---------------- alpha_src / alpha_dst --------------------------------------
template <int H, int F>
__global__ void k_alpha(const float* __restrict__ a_src, const float* __restrict__ a_dst) {
    int idx = blockIdx.x * blockDim.x + threadIdx.x;
    if (idx >= NN * H) return;
    int n = idx / H, h = idx - n * H;
    const float* hr = &g_h[n * 64 + h * F];
    float s = 0.f, d = 0.f;
#pragma unroll
    for (int f = 0; f < F; f++) {
        float v = hr[f];
        s += v * a_src[h * F + f];
        d += v * a_dst[h * F + f];
    }
    g_as[n * H + h] = s;
    g_ad[n * H + h] = d;
}

// ---------------- fused aggregation: max + softmax + weighted sum + elu ------
// warp per dst node, lane owns cols {2l, 2l+1}; writes g_x directly.
template <int H, int F>
__global__ void k_agg(const float* __restrict__ b) {
    int n = blockIdx.x * 8 + (threadIdx.x >> 5);
    if (n >= NN) return;
    int lane = threadIdx.x & 31;
    int c0 = lane * 2;
    int head = c0 / F;
    float ad_d = g_ad[n * H + head];
    float e_self = lrelu(g_as[n * H + head] + ad_d);
    int beg = g_off[n], end = g_off[n + 1];
    // pass 1: per-head max (all lanes of a head compute the same value)
    float m = e_self;
    for (int j = beg; j < end; j++) {
        int s = __ldg(&g_adj[j]);
        m = fmaxf(m, lrelu(__ldg(&g_as[s * H + head]) + ad_d));
    }
    // pass 2: denom + weighted aggregation (self-loop first)
    const float2* h2 = (const float2*)g_h;
    float den = __expf(e_self - m);
    float2 hv = h2[n * 32 + lane];
    float a0 = den * hv.x, a1 = den * hv.y;
    for (int j = beg; j < end; j++) {
        int s = __ldg(&g_adj[j]);
        float w = __expf(lrelu(__ldg(&g_as[s * H + head]) + ad_d) - m);
        den += w;
        float2 hs = h2[s * 32 + lane];
        a0 += w * hs.x;
        a1 += w * hs.y;
    }
    float inv = 1.f / den;
    float o0 = eluf(a0 * inv + b[c0]);
    float o1 = eluf(a1 * inv + b[c0 + 1]);
    ((float2*)g_x)[n * 32 + lane] = make_float2(o0, o1);
}

// ---------------- final scoring ----------------------------------------------
__global__ void k_score(const void* __restrict__ bu_, const void* __restrict__ bi_,
                        float* __restrict__ out) {
    int gid = blockIdx.x * blockDim.x + threadIdx.x;
    if (gid >= NB * 8) return;
    int p = gid >> 3, l = gid & 7;
    int u, it;
    if (g_is64) {
        u  = (int)((const long long*)bu_)[p];
        it = (int)((const long long*)bi_)[p];
    } else {
        u  = ((const int*)bu_)[p];
        it = ((const int*)bi_)[p];
    }
    const float* xu = &g_x[(long)u * 64];
    const float* xv = &g_x[((long)it + N_USERS) * 64];
    int o = l * 8;
    float acc = 0.f;
#pragma unroll
    for (int k = 0; k < 8; k++) acc += xu[o + k] * xv[o + k];
    acc += __shfl_xor_sync(0xffffffffu, acc, 1);
    acc += __shfl_xor_sync(0xffffffffu, acc, 2);
    acc += __shfl_xor_sync(0xffffffffu, acc, 4);
    if (l == 0) out[p] = 1.f / (1.f + expf(-acc));
}

// ---------------- host launcher ----------------------------------------------
extern "C" void kernel_launch(void* const* d_in, const int* in_sizes, int n_in,
                              void* d_out, int out_size) {
    const void *edge = nullptr, *bu = nullptr, *bi = nullptr;
    const float *ue = nullptr, *ie = nullptr, *W1 = nullptr, *W2 = nullptr;
    const float* v64[6] = {nullptr, nullptr, nullptr, nullptr, nullptr, nullptr};
    int c64 = 0;
    for (int i = 0; i < n_in; i++) {
        int sz = in_sizes[i];
        if      (sz == 2 * NE)        edge = d_in[i];
        else if (sz == NB)            { if (!bu) bu = d_in[i]; else bi = d_in[i]; }
        else if (sz == N_USERS * DD)  ue = (const float*)d_in[i];
        else if (sz == N_ITEMS * DD)  ie = (const float*)d_in[i];
        else if (sz == DD * DD)       { if (!W1) W1 = (const float*)d_in[i];
                                        else     W2 = (const float*)d_in[i]; }
        else if (sz == 64 && c64 < 6) v64[c64++] = (const float*)d_in[i];
    }
    const float *as1 = v64[0], *ad1 = v64[1], *b1 = v64[2];
    const float *as2 = v64[3], *ad2 = v64[4], *b2 = v64[5];

    const int TB = 256;
    const int EB = (NE + TB - 1) / TB;

    k_detect <<<1, 32>>>((const int*)edge);
    k_edges  <<<EB, TB>>>(edge);
    k_concat <<<(NN * 16 + TB - 1) / TB, TB>>>(ue, ie);

    // CSR build (dst-grouped)
    k_count  <<<EB, TB>>>();
    k_s1     <<<SB, 256>>>();
    k_s2     <<<1, 1024>>>();
    k_s3     <<<SB, 256>>>();
    k_scatter<<<EB, TB>>>();

    // ---- layer 1: H=4, F=16 ----
    k_gemm <<<(NN + 31) / 32, 128>>>(W1);
    k_alpha<4, 16><<<(NN * 4 + TB - 1) / TB, TB>>>(as1, ad1);
    k_agg  <4, 16><<<(NN + 7) / 8, TB>>>(b1);

    // ---- layer 2: H=1, F=64 ----
    k_gemm <<<(NN + 31) / 32, 128>>>(W2);
    k_alpha<1, 64><<<(NN + TB - 1) / TB, TB>>>(as2, ad2);
    k_agg  <1, 64><<<(NN + 7) / 8, TB>>>(b2);

    k_score<<<(NB * 8 + TB - 1) / TB, TB>>>(bu, bi, (float*)d_out);
}

// round 3
// speedup vs baseline: 1.8382x; 1.2142x over previous
#include <cuda_runtime.h>

#define N_USERS 100000
#define N_ITEMS 50000
#define NN      150000
#define NE      2000000
#define DD      64
#define NB      16384
#define SB      586      // ceil(NN/256) scan blocks

// ---------------- scratch (device globals) ----------------------------------
__device__ float g_x  [NN*DD];
__device__ float g_h  [NN*DD];
__device__ float g_as [NN*4];
__device__ float g_ad [NN*4];
__device__ int   g_adj[NE];      // CSR adjacency (src per slot, grouped by dst)
__device__ int   g_cnt[NN];
__device__ int   g_off[NN+1];
__device__ int   g_pos[NN];
__device__ int   g_spine[1024];
__device__ int   g_is64;

// ---------------- helpers ---------------------------------------------------
__device__ __forceinline__ float lrelu(float x) { return x > 0.f ? x : 0.2f * x; }
__device__ __forceinline__ float eluf (float v) { return v > 0.f ? v : expf(v) - 1.f; }

// ---------------- index dtype detection -------------------------------------
__global__ void k_detect(const int* __restrict__ ei) {
    if (threadIdx.x == 0) {
        int all0 = 1;
        for (int k = 0; k < 64; k++)
            if (ei[2 * k + 1] != 0) { all0 = 0; break; }
        g_is64 = all0;
    }
}

__global__ void k_zero() {
    int i = blockIdx.x * blockDim.x + threadIdx.x;
    if (i < NN) g_cnt[i] = 0;
}

// histogram of dst straight from the raw edge buffer
__global__ void k_count(const void* __restrict__ ei) {
    int e = blockIdx.x * blockDim.x + threadIdx.x;
    if (e >= NE) return;
    int d = g_is64 ? (int)((const long long*)ei)[NE + e]
                   : ((const int*)ei)[NE + e];
    atomicAdd(&g_cnt[d], 1);
}

__global__ void k_s1() {                       // block sums -> spine
    __shared__ int sm[256];
    int i = blockIdx.x * 256 + threadIdx.x;
    sm[threadIdx.x] = (i < NN) ? g_cnt[i] : 0;
    __syncthreads();
    for (int s = 128; s > 0; s >>= 1) {
        if (threadIdx.x < s) sm[threadIdx.x] += sm[threadIdx.x + s];
        __syncthreads();
    }
    if (threadIdx.x == 0) g_spine[blockIdx.x] = sm[0];
}

__global__ void k_s2() {                       // exclusive scan of spine
    __shared__ int sm[1024];
    int t = threadIdx.x;
    sm[t] = (t < SB) ? g_spine[t] : 0;
    __syncthreads();
    for (int d = 1; d < 1024; d <<= 1) {
        int v = (t >= d) ? sm[t - d] : 0;
        __syncthreads();
        sm[t] += v;
        __syncthreads();
    }
    g_spine[t] = (t == 0) ? 0 : sm[t - 1];
    if (t == 0) g_off[NN] = NE;
}

__global__ void k_s3() {                       // per-block exclusive scan + spine offset
    __shared__ int sm[256];
    int t = threadIdx.x;
    int i = blockIdx.x * 256 + t;
    int v = (i < NN) ? g_cnt[i] : 0;
    sm[t] = v;
    __syncthreads();
    for (int d = 1; d < 256; d <<= 1) {
        int u = (t >= d) ? sm[t - d] : 0;
        __syncthreads();
        sm[t] += u;
        __syncthreads();
    }
    int excl = sm[t] - v + g_spine[blockIdx.x];
    if (i < NN) { g_off[i] = excl; g_pos[i] = excl; }
}

__global__ void k_scatter(const void* __restrict__ ei) {
    int e = blockIdx.x * blockDim.x + threadIdx.x;
    if (e >= NE) return;
    int s, d;
    if (g_is64) {
        const long long* p = (const long long*)ei;
        s = (int)p[e]; d = (int)p[NE + e];
    } else {
        const int* p = (const int*)ei;
        s = p[e]; d = p[NE + e];
    }
    int pos = atomicAdd(&g_pos[d], 1);
    g_adj[pos] = s;
}

// ---------------- GEMM: h = src @ W, 4x4 register blocking -------------------
// 128 threads, 32 nodes x 64 cols per block.
template <bool FIRST>
__global__ void k_gemm(const float* __restrict__ W,
                       const float* __restrict__ ue,
                       const float* __restrict__ ie) {
    __shared__ float sW[64 * 64];
    __shared__ float sxT[64][32];
    int t = threadIdx.x;
#pragma unroll
    for (int i = 0; i < 8; i++)
        *(float4*)&sW[(t + 128 * i) * 4] = *(const float4*)&W[(t + 128 * i) * 4];
    int n0 = blockIdx.x * 32;
#pragma unroll
    for (int i = 0; i < 4; i++) {
        int f = t + 128 * i;           // float4 slot 0..511
        int node = f >> 4;
        int col  = (f & 15) * 4;
        int n = n0 + node;
        float4 v = make_float4(0.f, 0.f, 0.f, 0.f);
        if (n < NN) {
            const float* row = FIRST
                ? (n < N_USERS ? ue + (size_t)n * 64
                               : ie + (size_t)(n - N_USERS) * 64)
                : g_x + (size_t)n * 64;
            v = *(const float4*)(row + col);
        }
        sxT[col + 0][node] = v.x; sxT[col + 1][node] = v.y;
        sxT[col + 2][node] = v.z; sxT[col + 3][node] = v.w;
    }
    __syncthreads();
    int ng = t >> 4;      // node group 0..7 (4 nodes each)
    int cg = t & 15;      // col group 0..15 (4 cols each)
    float acc[4][4];
#pragma unroll
    for (int i = 0; i < 4; i++)
#pragma unroll
        for (int j = 0; j < 4; j++) acc[i][j] = 0.f;
#pragma unroll 8
    for (int k = 0; k < 64; k++) {
        float4 xv = *(float4*)&sxT[k][ng * 4];
        float4 wv = *(float4*)&sW[k * 64 + cg * 4];
        acc[0][0] += xv.x * wv.x; acc[0][1] += xv.x * wv.y;
        acc[0][2] += xv.x * wv.z; acc[0][3] += xv.x * wv.w;
        acc[1][0] += xv.y * wv.x; acc[1][1] += xv.y * wv.y;
        acc[1][2] += xv.y * wv.z; acc[1][3] += xv.y * wv.w;
        acc[2][0] += xv.z * wv.x; acc[2][1] += xv.z * wv.y;
        acc[2][2] += xv.z * wv.z; acc[2][3] += xv.z * wv.w;
        acc[3][0] += xv.w * wv.x; acc[3][1] += xv.w * wv.y;
        acc[3][2] += xv.w * wv.z; acc[3][3] += xv.w * wv.w;
    }
#pragma unroll
    for (int i = 0; i < 4; i++) {
        int n = n0 + ng * 4 + i;
        if (n < NN)
            *(float4*)&g_h[(size_t)n * 64 + cg * 4] =
                make_float4(acc[i][0], acc[i][1], acc[i][2], acc[i][3]);
    }
}

// ---------------- alpha_src / alpha_dst --------------------------------------
template <int H, int F>
__global__ void k_alpha(const float* __restrict__ a_src, const float* __restrict__ a_dst) {
    int idx = blockIdx.x * blockDim.x + threadIdx.x;
    if (idx >= NN * H) return;
    int n = idx / H, h = idx - n * H;
    const float* hr = &g_h[n * 64 + h * F];
    float s = 0.f, d = 0.f;
#pragma unroll
    for (int f = 0; f < F; f++) {
        float v = hr[f];
        s += v * a_src[h * F + f];
        d += v * a_dst[h * F + f];
    }
    g_as[n * H + h] = s;
    g_ad[n * H + h] = d;
}

// ---------------- fused aggregation: softmax + weighted sum + elu ------------
// Single pass (no max shift: logits are O(0.1), exp is safe; softmax is
// shift-invariant so the result is identical up to fp rounding).
// Warp per dst node, lane owns cols {2l, 2l+1}. 4x unrolled gather.
template <int H, int F>
__global__ void k_agg(const float* __restrict__ b) {
    int n = blockIdx.x * 8 + (threadIdx.x >> 5);
    if (n >= NN) return;
    int lane = threadIdx.x & 31;
    int c0 = lane * 2;
    int head = c0 / F;
    float ad_d = g_ad[n * H + head];
    const float2* h2 = (const float2*)g_h;
    float den = __expf(lrelu(g_as[n * H + head] + ad_d));   // self-loop
    float2 hv = h2[(size_t)n * 32 + lane];
    float a0 = den * hv.x, a1 = den * hv.y;
    int beg = g_off[n], end = g_off[n + 1];
    int j = beg;
    for (; j + 4 <= end; j += 4) {
        int s0 = __ldg(&g_adj[j + 0]);
        int s1 = __ldg(&g_adj[j + 1]);
        int s2 = __ldg(&g_adj[j + 2]);
        int s3 = __ldg(&g_adj[j + 3]);
        float w0 = __expf(lrelu(__ldg(&g_as[s0 * H + head]) + ad_d));
        float w1 = __expf(lrelu(__ldg(&g_as[s1 * H + head]) + ad_d));
        float w2 = __expf(lrelu(__ldg(&g_as[s2 * H + head]) + ad_d));
        float w3 = __expf(lrelu(__ldg(&g_as[s3 * H + head]) + ad_d));
        float2 p0 = h2[(size_t)s0 * 32 + lane];
        float2 p1 = h2[(size_t)s1 * 32 + lane];
        float2 p2 = h2[(size_t)s2 * 32 + lane];
        float2 p3 = h2[(size_t)s3 * 32 + lane];
        den += (w0 + w1) + (w2 + w3);
        a0 += w0 * p0.x; a1 += w0 * p0.y;
        a0 += w1 * p1.x; a1 += w1 * p1.y;
        a0 += w2 * p2.x; a1 += w2 * p2.y;
        a0 += w3 * p3.x; a1 += w3 * p3.y;
    }
    for (; j < end; j++) {
        int s = __ldg(&g_adj[j]);
        float w = __expf(lrelu(__ldg(&g_as[s * H + head]) + ad_d));
        float2 p = h2[(size_t)s * 32 + lane];
        den += w; a0 += w * p.x; a1 += w * p.y;
    }
    float inv = 1.f / den;
    float o0 = eluf(a0 * inv + b[c0]);
    float o1 = eluf(a1 * inv + b[c0 + 1]);
    ((float2*)g_x)[(size_t)n * 32 + lane] = make_float2(o0, o1);
}

// ---------------- final scoring ----------------------------------------------
__global__ void k_score(const void* __restrict__ bu_, const void* __restrict__ bi_,
                        float* __restrict__ out) {
    int gid = blockIdx.x * blockDim.x + threadIdx.x;
    if (gid >= NB * 8) return;
    int p = gid >> 3, l = gid & 7;
    int u, it;
    if (g_is64) {
        u  = (int)((const long long*)bu_)[p];
        it = (int)((const long long*)bi_)[p];
    } else {
        u  = ((const int*)bu_)[p];
        it = ((const int*)bi_)[p];
    }
    const float* xu = &g_x[(long)u * 64];
    const float* xv = &g_x[((long)it + N_USERS) * 64];
    int o = l * 8;
    float acc = 0.f;
#pragma unroll
    for (int k = 0; k < 8; k++) acc += xu[o + k] * xv[o + k];
    acc += __shfl_xor_sync(0xffffffffu, acc, 1);
    acc += __shfl_xor_sync(0xffffffffu, acc, 2);
    acc += __shfl_xor_sync(0xffffffffu, acc, 4);
    if (l == 0) out[p] = 1.f / (1.f + expf(-acc));
}

// ---------------- host launcher ----------------------------------------------
extern "C" void kernel_launch(void* const* d_in, const int* in_sizes, int n_in,
                              void* d_out, int out_size) {
    const void *edge = nullptr, *bu = nullptr, *bi = nullptr;
    const float *ue = nullptr, *ie = nullptr, *W1 = nullptr, *W2 = nullptr;
    const float* v64[6] = {nullptr, nullptr, nullptr, nullptr, nullptr, nullptr};
    int c64 = 0;
    for (int i = 0; i < n_in; i++) {
        int sz = in_sizes[i];
        if      (sz == 2 * NE)        edge = d_in[i];
        else if (sz == NB)            { if (!bu) bu = d_in[i]; else bi = d_in[i]; }
        else if (sz == N_USERS * DD)  ue = (const float*)d_in[i];
        else if (sz == N_ITEMS * DD)  ie = (const float*)d_in[i];
        else if (sz == DD * DD)       { if (!W1) W1 = (const float*)d_in[i];
                                        else     W2 = (const float*)d_in[i]; }
        else if (sz == 64 && c64 < 6) v64[c64++] = (const float*)d_in[i];
    }
    const float *as1 = v64[0], *ad1 = v64[1], *b1 = v64[2];
    const float *as2 = v64[3], *ad2 = v64[4], *b2 = v64[5];

    const int TB = 256;
    const int EB = (NE + TB - 1) / TB;

    k_detect <<<1, 32>>>((const int*)edge);
    k_zero   <<<(NN + TB - 1) / TB, TB>>>();
    k_count  <<<EB, TB>>>(edge);
    k_s1     <<<SB, 256>>>();
    k_s2     <<<1, 1024>>>();
    k_s3     <<<SB, 256>>>();
    k_scatter<<<EB, TB>>>(edge);

    // ---- layer 1: H=4, F=16 ----
    k_gemm<true>  <<<(NN + 31) / 32, 128>>>(W1, ue, ie);
    k_alpha<4, 16><<<(NN * 4 + TB - 1) / TB, TB>>>(as1, ad1);
    k_agg  <4, 16><<<(NN + 7) / 8, TB>>>(b1);

    // ---- layer 2: H=1, F=64 ----
    k_gemm<false> <<<(NN + 31) / 32, 128>>>(W2, nullptr, nullptr);
    k_alpha<1, 64><<<(NN + TB - 1) / TB, TB>>>(as2, ad2);
    k_agg  <1, 64><<<(NN + 7) / 8, TB>>>(b2);

    k_score<<<(NB * 8 + TB - 1) / TB, TB>>>(bu, bi, (float*)d_out);
}

// round 4
// speedup vs baseline: 1.8799x; 1.0227x over previous
#include <cuda_runtime.h>

#define N_USERS 100000
#define N_ITEMS 50000
#define NN      150000
#define NE      2000000
#define DD      64
#define NB      16384
#define SB      586      // ceil(NN/256) scan blocks

// ---------------- scratch (device globals) ----------------------------------
__device__ float g_x  [NN*DD];
__device__ float g_h  [NN*DD];
__device__ float g_as [NN*4];
__device__ float g_ad [NN*4];
__device__ int   g_adj[NE];      // CSR adjacency (src per slot, grouped by dst)
__device__ int   g_cnt[NN];
__device__ int   g_off[NN+1];
__device__ int   g_pos[NN];
__device__ int   g_spine[1024];
__device__ int   g_is64;

// ---------------- helpers ---------------------------------------------------
__device__ __forceinline__ float lrelu(float x) { return x > 0.f ? x : 0.2f * x; }
__device__ __forceinline__ float eluf (float v) { return v > 0.f ? v : expf(v) - 1.f; }

// ---------------- index dtype detection -------------------------------------
__global__ void k_detect(const int* __restrict__ ei) {
    if (threadIdx.x == 0) {
        int all0 = 1;
        for (int k = 0; k < 64; k++)
            if (ei[2 * k + 1] != 0) { all0 = 0; break; }
        g_is64 = all0;
    }
}

__global__ void k_zero() {
    int i = blockIdx.x * blockDim.x + threadIdx.x;
    if (i < NN) g_cnt[i] = 0;
}

// histogram of dst straight from the raw edge buffer
__global__ void k_count(const void* __restrict__ ei) {
    int e = blockIdx.x * blockDim.x + threadIdx.x;
    if (e >= NE) return;
    int d = g_is64 ? (int)((const long long*)ei)[NE + e]
                   : ((const int*)ei)[NE + e];
    atomicAdd(&g_cnt[d], 1);
}

__global__ void k_s1() {                       // block sums -> spine
    __shared__ int sm[256];
    int i = blockIdx.x * 256 + threadIdx.x;
    sm[threadIdx.x] = (i < NN) ? g_cnt[i] : 0;
    __syncthreads();
    for (int s = 128; s > 0; s >>= 1) {
        if (threadIdx.x < s) sm[threadIdx.x] += sm[threadIdx.x + s];
        __syncthreads();
    }
    if (threadIdx.x == 0) g_spine[blockIdx.x] = sm[0];
}

__global__ void k_s2() {                       // exclusive scan of spine
    __shared__ int sm[1024];
    int t = threadIdx.x;
    sm[t] = (t < SB) ? g_spine[t] : 0;
    __syncthreads();
    for (int d = 1; d < 1024; d <<= 1) {
        int v = (t >= d) ? sm[t - d] : 0;
        __syncthreads();
        sm[t] += v;
        __syncthreads();
    }
    g_spine[t] = (t == 0) ? 0 : sm[t - 1];
    if (t == 0) g_off[NN] = NE;
}

__global__ void k_s3() {                       // per-block exclusive scan + spine offset
    __shared__ int sm[256];
    int t = threadIdx.x;
    int i = blockIdx.x * 256 + t;
    int v = (i < NN) ? g_cnt[i] : 0;
    sm[t] = v;
    __syncthreads();
    for (int d = 1; d < 256; d <<= 1) {
        int u = (t >= d) ? sm[t - d] : 0;
        __syncthreads();
        sm[t] += u;
        __syncthreads();
    }
    int excl = sm[t] - v + g_spine[blockIdx.x];
    if (i < NN) { g_off[i] = excl; g_pos[i] = excl; }
}

__global__ void k_scatter(const void* __restrict__ ei) {
    int e = blockIdx.x * blockDim.x + threadIdx.x;
    if (e >= NE) return;
    int s, d;
    if (g_is64) {
        const long long* p = (const long long*)ei;
        s = (int)p[e]; d = (int)p[NE + e];
    } else {
        const int* p = (const int*)ei;
        s = p[e]; d = p[NE + e];
    }
    int pos = atomicAdd(&g_pos[d], 1);
    g_adj[pos] = s;
}

// ---------------- GEMM: h = src @ W, 4x4 register blocking -------------------
template <bool FIRST>
__global__ void k_gemm(const float* __restrict__ W,
                       const float* __restrict__ ue,
                       const float* __restrict__ ie) {
    __shared__ float sW[64 * 64];
    __shared__ float sxT[64][32];
    int t = threadIdx.x;
#pragma unroll
    for (int i = 0; i < 8; i++)
        *(float4*)&sW[(t + 128 * i) * 4] = *(const float4*)&W[(t + 128 * i) * 4];
    int n0 = blockIdx.x * 32;
#pragma unroll
    for (int i = 0; i < 4; i++) {
        int f = t + 128 * i;           // float4 slot 0..511
        int node = f >> 4;
        int col  = (f & 15) * 4;
        int n = n0 + node;
        float4 v = make_float4(0.f, 0.f, 0.f, 0.f);
        if (n < NN) {
            const float* row = FIRST
                ? (n < N_USERS ? ue + (size_t)n * 64
                               : ie + (size_t)(n - N_USERS) * 64)
                : g_x + (size_t)n * 64;
            v = *(const float4*)(row + col);
        }
        sxT[col + 0][node] = v.x; sxT[col + 1][node] = v.y;
        sxT[col + 2][node] = v.z; sxT[col + 3][node] = v.w;
    }
    __syncthreads();
    int ng = t >> 4;      // node group 0..7 (4 nodes each)
    int cg = t & 15;      // col group 0..15 (4 cols each)
    float acc[4][4];
#pragma unroll
    for (int i = 0; i < 4; i++)
#pragma unroll
        for (int j = 0; j < 4; j++) acc[i][j] = 0.f;
#pragma unroll 8
    for (int k = 0; k < 64; k++) {
        float4 xv = *(float4*)&sxT[k][ng * 4];
        float4 wv = *(float4*)&sW[k * 64 + cg * 4];
        acc[0][0] += xv.x * wv.x; acc[0][1] += xv.x * wv.y;
        acc[0][2] += xv.x * wv.z; acc[0][3] += xv.x * wv.w;
        acc[1][0] += xv.y * wv.x; acc[1][1] += xv.y * wv.y;
        acc[1][2] += xv.y * wv.z; acc[1][3] += xv.y * wv.w;
        acc[2][0] += xv.z * wv.x; acc[2][1] += xv.z * wv.y;
        acc[2][2] += xv.z * wv.z; acc[2][3] += xv.z * wv.w;
        acc[3][0] += xv.w * wv.x; acc[3][1] += xv.w * wv.y;
        acc[3][2] += xv.w * wv.z; acc[3][3] += xv.w * wv.w;
    }
#pragma unroll
    for (int i = 0; i < 4; i++) {
        int n = n0 + ng * 4 + i;
        if (n < NN)
            *(float4*)&g_h[(size_t)n * 64 + cg * 4] =
                make_float4(acc[i][0], acc[i][1], acc[i][2], acc[i][3]);
    }
}

// ---------------- alpha_src / alpha_dst --------------------------------------
template <int H, int F>
__global__ void k_alpha(const float* __restrict__ a_src, const float* __restrict__ a_dst) {
    int idx = blockIdx.x * blockDim.x + threadIdx.x;
    if (idx >= NN * H) return;
    int n = idx / H, h = idx - n * H;
    const float* hr = &g_h[n * 64 + h * F];
    float s = 0.f, d = 0.f;
#pragma unroll
    for (int f = 0; f < F; f++) {
        float v = hr[f];
        s += v * a_src[h * F + f];
        d += v * a_dst[h * F + f];
    }
    g_as[n * H + h] = s;
    g_ad[n * H + h] = d;
}

// ---------------- fused aggregation (cooperative two-phase) ------------------
// Warp per dst node. Phase 1: lanes compute exp-weights for 32 neighbors in
// parallel (coalesced adj read, one exp per (neighbor,head)), staged in smem.
// Phase 2: 4-wide rounds gather h[src] float2 per lane with weights from smem.
template <int H, int F>
__global__ void k_agg(const float* __restrict__ b) {
    __shared__ int   s_s[8][32];
    __shared__ float s_w[8][H * 32];
    int wrp  = threadIdx.x >> 5;
    int n    = blockIdx.x * 8 + wrp;
    if (n >= NN) return;
    int lane = threadIdx.x & 31;
    int c0   = lane * 2;
    int head = c0 / F;
    const float2* h2 = (const float2*)g_h;

    float4 adv;
    float  ad1s = 0.f;
    float  den;
    if (H == 4) {
        adv = *(const float4*)&g_ad[n * 4];
        float4 asv = *(const float4*)&g_as[n * 4];
        float adh = head == 0 ? adv.x : head == 1 ? adv.y : head == 2 ? adv.z : adv.w;
        float ash = head == 0 ? asv.x : head == 1 ? asv.y : head == 2 ? asv.z : asv.w;
        den = __expf(lrelu(ash + adh));
    } else {
        ad1s = g_ad[n];
        den  = __expf(lrelu(g_as[n] + ad1s));
    }
    float2 hv = h2[(size_t)n * 32 + lane];
    float a0 = den * hv.x, a1 = den * hv.y;

    int beg = g_off[n], end = g_off[n + 1];
    for (int base = beg; base < end; base += 32) {
        int cnt = end - base; if (cnt > 32) cnt = 32;
        int s = n;
        if (lane < cnt) s = __ldg(&g_adj[base + lane]);
        s_s[wrp][lane] = s;
        if (H == 4) {
            float4 asv = *(const float4*)&g_as[s * 4];
            float w0 = 0.f, w1 = 0.f, w2 = 0.f, w3 = 0.f;
            if (lane < cnt) {
                w0 = __expf(lrelu(asv.x + adv.x));
                w1 = __expf(lrelu(asv.y + adv.y));
                w2 = __expf(lrelu(asv.z + adv.z));
                w3 = __expf(lrelu(asv.w + adv.w));
            }
            s_w[wrp][ 0 + lane] = w0;
            s_w[wrp][32 + lane] = w1;
            s_w[wrp][64 + lane] = w2;
            s_w[wrp][96 + lane] = w3;
        } else {
            float asv = __ldg(&g_as[s]);
            s_w[wrp][lane] = (lane < cnt) ? __expf(lrelu(asv + ad1s)) : 0.f;
        }
        __syncwarp();
        int rounds = (cnt + 3) >> 2;
        const float* wbase = &s_w[wrp][head * 32];
        for (int r = 0; r < rounds; r++) {
            int j = r * 4;
            int4   sv = *(const int4*)  &s_s[wrp][j];
            float4 wv = *(const float4*)&wbase[j];
            float2 pA = h2[(size_t)sv.x * 32 + lane];
            float2 pB = h2[(size_t)sv.y * 32 + lane];
            float2 pC = h2[(size_t)sv.z * 32 + lane];
            float2 pD = h2[(size_t)sv.w * 32 + lane];
            den += (wv.x + wv.y) + (wv.z + wv.w);
            a0 += wv.x * pA.x; a1 += wv.x * pA.y;
            a0 += wv.y * pB.x; a1 += wv.y * pB.y;
            a0 += wv.z * pC.x; a1 += wv.z * pC.y;
            a0 += wv.w * pD.x; a1 += wv.w * pD.y;
        }
        __syncwarp();
    }
    float inv = 1.f / den;
    float o0 = eluf(a0 * inv + b[c0]);
    float o1 = eluf(a1 * inv + b[c0 + 1]);
    ((float2*)g_x)[(size_t)n * 32 + lane] = make_float2(o0, o1);
}

// ---------------- final scoring ----------------------------------------------
__global__ void k_score(const void* __restrict__ bu_, const void* __restrict__ bi_,
                        float* __restrict__ out) {
    int gid = blockIdx.x * blockDim.x + threadIdx.x;
    if (gid >= NB * 8) return;
    int p = gid >> 3, l = gid & 7;
    int u, it;
    if (g_is64) {
        u  = (int)((const long long*)bu_)[p];
        it = (int)((const long long*)bi_)[p];
    } else {
        u  = ((const int*)bu_)[p];
        it = ((const int*)bi_)[p];
    }
    const float* xu = &g_x[(long)u * 64];
    const float* xv = &g_x[((long)it + N_USERS) * 64];
    int o = l * 8;
    float acc = 0.f;
#pragma unroll
    for (int k = 0; k < 8; k++) acc += xu[o + k] * xv[o + k];
    acc += __shfl_xor_sync(0xffffffffu, acc, 1);
    acc += __shfl_xor_sync(0xffffffffu, acc, 2);
    acc += __shfl_xor_sync(0xffffffffu, acc, 4);
    if (l == 0) out[p] = 1.f / (1.f + expf(-acc));
}

// ---------------- host launcher ----------------------------------------------
extern "C" void kernel_launch(void* const* d_in, const int* in_sizes, int n_in,
                              void* d_out, int out_size) {
    const void *edge = nullptr, *bu = nullptr, *bi = nullptr;
    const float *ue = nullptr, *ie = nullptr, *W1 = nullptr, *W2 = nullptr;
    const float* v64[6] = {nullptr, nullptr, nullptr, nullptr, nullptr, nullptr};
    int c64 = 0;
    for (int i = 0; i < n_in; i++) {
        int sz = in_sizes[i];
        if      (sz == 2 * NE)        edge = d_in[i];
        else if (sz == NB)            { if (!bu) bu = d_in[i]; else bi = d_in[i]; }
        else if (sz == N_USERS * DD)  ue = (const float*)d_in[i];
        else if (sz == N_ITEMS * DD)  ie = (const float*)d_in[i];
        else if (sz == DD * DD)       { if (!W1) W1 = (const float*)d_in[i];
                                        else     W2 = (const float*)d_in[i]; }
        else if (sz == 64 && c64 < 6) v64[c64++] = (const float*)d_in[i];
    }
    const float *as1 = v64[0], *ad1 = v64[1], *b1 = v64[2];
    const float *as2 = v64[3], *ad2 = v64[4], *b2 = v64[5];

    const int TB = 256;
    const int EB = (NE + TB - 1) / TB;

    k_detect <<<1, 32>>>((const int*)edge);
    k_zero   <<<(NN + TB - 1) / TB, TB>>>();
    k_count  <<<EB, TB>>>(edge);
    k_s1     <<<SB, 256>>>();
    k_s2     <<<1, 1024>>>();
    k_s3     <<<SB, 256>>>();
    k_scatter<<<EB, TB>>>(edge);

    // ---- layer 1: H=4, F=16 ----
    k_gemm<true>  <<<(NN + 31) / 32, 128>>>(W1, ue, ie);
    k_alpha<4, 16><<<(NN * 4 + TB - 1) / TB, TB>>>(as1, ad1);
    k_agg  <4, 16><<<(NN + 7) / 8, TB>>>(b1);

    // ---- layer 2: H=1, F=64 ----
    k_gemm<false> <<<(NN + 31) / 32, 128>>>(W2, nullptr, nullptr);
    k_alpha<1, 64><<<(NN + TB - 1) / TB, TB>>>(as2, ad2);
    k_agg  <1, 64><<<(NN + 7) / 8, TB>>>(b2);

    k_score<<<(NB * 8 + TB - 1) / TB, TB>>>(bu, bi, (float*)d_out);
}

// round 5
// speedup vs baseline: 2.0771x; 1.1049x over previous
#include <cuda_runtime.h>
#include <cuda_bf16.h>

#define N_USERS 100000
#define N_ITEMS 50000
#define NN      150000
#define NE      2000000
#define DD      64
#define NB      16384
#define SB      586      // ceil(NN/256) scan blocks

// ---------------- scratch (device globals) ----------------------------------
__device__ float          g_x [NN*DD];    // layer outputs (fp32)
__device__ __nv_bfloat16  g_hb[NN*DD];    // h = x@W in bf16 (gather payload)
__device__ float g_as [NN*4];
__device__ float g_ad [NN*4];
__device__ int   g_adj[NE];
__device__ int   g_cnt[NN];
__device__ int   g_off[NN+1];
__device__ int   g_pos[NN];
__device__ int   g_spine[1024];
__device__ int   g_is64;

// ---------------- helpers ---------------------------------------------------
__device__ __forceinline__ float lrelu(float x) { return x > 0.f ? x : 0.2f * x; }
__device__ __forceinline__ float eluf (float v) { return v > 0.f ? v : expf(v) - 1.f; }

// ---------------- init: zero counters + dtype detect -------------------------
__global__ void k_init(const int* __restrict__ ei) {
    int i = blockIdx.x * blockDim.x + threadIdx.x;
    if (i < NN) g_cnt[i] = 0;
    if (blockIdx.x == 0 && threadIdx.x == 0) {
        int all0 = 1;
        for (int k = 0; k < 64; k++)
            if (ei[2 * k + 1] != 0) { all0 = 0; break; }
        g_is64 = all0;
    }
}

__global__ void k_count(const void* __restrict__ ei) {
    int e = blockIdx.x * blockDim.x + threadIdx.x;
    if (e >= NE) return;
    int d = g_is64 ? (int)((const long long*)ei)[NE + e]
                   : ((const int*)ei)[NE + e];
    atomicAdd(&g_cnt[d], 1);
}

__global__ void k_s1() {
    __shared__ int sm[256];
    int i = blockIdx.x * 256 + threadIdx.x;
    sm[threadIdx.x] = (i < NN) ? g_cnt[i] : 0;
    __syncthreads();
    for (int s = 128; s > 0; s >>= 1) {
        if (threadIdx.x < s) sm[threadIdx.x] += sm[threadIdx.x + s];
        __syncthreads();
    }
    if (threadIdx.x == 0) g_spine[blockIdx.x] = sm[0];
}

__global__ void k_s2() {
    __shared__ int sm[1024];
    int t = threadIdx.x;
    sm[t] = (t < SB) ? g_spine[t] : 0;
    __syncthreads();
    for (int d = 1; d < 1024; d <<= 1) {
        int v = (t >= d) ? sm[t - d] : 0;
        __syncthreads();
        sm[t] += v;
        __syncthreads();
    }
    g_spine[t] = (t == 0) ? 0 : sm[t - 1];
    if (t == 0) g_off[NN] = NE;
}

__global__ void k_s3() {
    __shared__ int sm[256];
    int t = threadIdx.x;
    int i = blockIdx.x * 256 + t;
    int v = (i < NN) ? g_cnt[i] : 0;
    sm[t] = v;
    __syncthreads();
    for (int d = 1; d < 256; d <<= 1) {
        int u = (t >= d) ? sm[t - d] : 0;
        __syncthreads();
        sm[t] += u;
        __syncthreads();
    }
    int excl = sm[t] - v + g_spine[blockIdx.x];
    if (i < NN) { g_off[i] = excl; g_pos[i] = excl; }
}

__global__ void k_scatter(const void* __restrict__ ei) {
    int e = blockIdx.x * blockDim.x + threadIdx.x;
    if (e >= NE) return;
    int s, d;
    if (g_is64) {
        const long long* p = (const long long*)ei;
        s = (int)p[e]; d = (int)p[NE + e];
    } else {
        const int* p = (const int*)ei;
        s = p[e]; d = p[NE + e];
    }
    int pos = atomicAdd(&g_pos[d], 1);
    g_adj[pos] = s;
}

// ---------------- fused GEMM + alpha ------------------------------------------
// h = src @ W (4x4 register blocking), write h in bf16, and compute
// as = h . a_src, ad = h . a_dst per head via shuffle reduction (fp32 accs).
template <bool FIRST, int H, int F>
__global__ void k_gemm(const float* __restrict__ W,
                       const float* __restrict__ ue,
                       const float* __restrict__ ie,
                       const float* __restrict__ a_src,
                       const float* __restrict__ a_dst) {
    __shared__ float sW[64 * 64];
    __shared__ float sxT[64][32];
    int t = threadIdx.x;
#pragma unroll
    for (int i = 0; i < 8; i++)
        *(float4*)&sW[(t + 128 * i) * 4] = *(const float4*)&W[(t + 128 * i) * 4];
    int n0 = blockIdx.x * 32;
#pragma unroll
    for (int i = 0; i < 4; i++) {
        int f = t + 128 * i;
        int node = f >> 4;
        int col  = (f & 15) * 4;
        int n = n0 + node;
        float4 v = make_float4(0.f, 0.f, 0.f, 0.f);
        if (n < NN) {
            const float* row = FIRST
                ? (n < N_USERS ? ue + (size_t)n * 64
                               : ie + (size_t)(n - N_USERS) * 64)
                : g_x + (size_t)n * 64;
            v = *(const float4*)(row + col);
        }
        sxT[col + 0][node] = v.x; sxT[col + 1][node] = v.y;
        sxT[col + 2][node] = v.z; sxT[col + 3][node] = v.w;
    }
    __syncthreads();
    int ng = t >> 4;      // node group 0..7 (4 nodes)
    int cg = t & 15;      // col group 0..15 (4 cols)
    float acc[4][4];
#pragma unroll
    for (int i = 0; i < 4; i++)
#pragma unroll
        for (int j = 0; j < 4; j++) acc[i][j] = 0.f;
#pragma unroll 8
    for (int k = 0; k < 64; k++) {
        float4 xv = *(float4*)&sxT[k][ng * 4];
        float4 wv = *(float4*)&sW[k * 64 + cg * 4];
        acc[0][0] += xv.x * wv.x; acc[0][1] += xv.x * wv.y;
        acc[0][2] += xv.x * wv.z; acc[0][3] += xv.x * wv.w;
        acc[1][0] += xv.y * wv.x; acc[1][1] += xv.y * wv.y;
        acc[1][2] += xv.y * wv.z; acc[1][3] += xv.y * wv.w;
        acc[2][0] += xv.z * wv.x; acc[2][1] += xv.z * wv.y;
        acc[2][2] += xv.z * wv.z; acc[2][3] += xv.z * wv.w;
        acc[3][0] += xv.w * wv.x; acc[3][1] += xv.w * wv.y;
        acc[3][2] += xv.w * wv.z; acc[3][3] += xv.w * wv.w;
    }
    // write h in bf16
#pragma unroll
    for (int i = 0; i < 4; i++) {
        int n = n0 + ng * 4 + i;
        if (n < NN) {
            __nv_bfloat162 p0 = __float22bfloat162_rn(make_float2(acc[i][0], acc[i][1]));
            __nv_bfloat162 p1 = __float22bfloat162_rn(make_float2(acc[i][2], acc[i][3]));
            uint2 pk;
            pk.x = *(unsigned*)&p0;
            pk.y = *(unsigned*)&p1;
            *(uint2*)&g_hb[(size_t)n * 64 + cg * 4] = pk;
        }
    }
    // fused alpha: partial dots over this thread's 4 cols, shuffle-reduce
    float4 av = *(const float4*)&a_src[cg * 4];
    float4 dv = *(const float4*)&a_dst[cg * 4];
    float ps[4], pd[4];
#pragma unroll
    for (int i = 0; i < 4; i++) {
        ps[i] = acc[i][0]*av.x + acc[i][1]*av.y + acc[i][2]*av.z + acc[i][3]*av.w;
        pd[i] = acc[i][0]*dv.x + acc[i][1]*dv.y + acc[i][2]*dv.z + acc[i][3]*dv.w;
    }
    if (H == 4) {
        // reduce within quads of lanes (cols 16/head)
#pragma unroll
        for (int i = 0; i < 4; i++) {
            ps[i] += __shfl_xor_sync(0xffffffffu, ps[i], 1);
            ps[i] += __shfl_xor_sync(0xffffffffu, ps[i], 2);
            pd[i] += __shfl_xor_sync(0xffffffffu, pd[i], 1);
            pd[i] += __shfl_xor_sync(0xffffffffu, pd[i], 2);
        }
        if ((cg & 3) == 0) {
            int head = cg >> 2;
#pragma unroll
            for (int i = 0; i < 4; i++) {
                int n = n0 + ng * 4 + i;
                if (n < NN) {
                    g_as[n * 4 + head] = ps[i];
                    g_ad[n * 4 + head] = pd[i];
                }
            }
        }
    } else {
#pragma unroll
        for (int i = 0; i < 4; i++) {
            ps[i] += __shfl_xor_sync(0xffffffffu, ps[i], 1);
            ps[i] += __shfl_xor_sync(0xffffffffu, ps[i], 2);
            ps[i] += __shfl_xor_sync(0xffffffffu, ps[i], 4);
            ps[i] += __shfl_xor_sync(0xffffffffu, ps[i], 8);
            pd[i] += __shfl_xor_sync(0xffffffffu, pd[i], 1);
            pd[i] += __shfl_xor_sync(0xffffffffu, pd[i], 2);
            pd[i] += __shfl_xor_sync(0xffffffffu, pd[i], 4);
            pd[i] += __shfl_xor_sync(0xffffffffu, pd[i], 8);
        }
        if (cg == 0) {
#pragma unroll
            for (int i = 0; i < 4; i++) {
                int n = n0 + ng * 4 + i;
                if (n < NN) { g_as[n] = ps[i]; g_ad[n] = pd[i]; }
            }
        }
    }
}

// ---------------- fused aggregation (uniform-broadcast loop, bf16 gathers) ---
// Warp per dst node, lane owns cols {2l, 2l+1}. 8/4/1-tier unroll for MLP.
template <int H, int F>
__global__ void k_agg(const float* __restrict__ b) {
    int n = blockIdx.x * 8 + (threadIdx.x >> 5);
    if (n >= NN) return;
    int lane = threadIdx.x & 31;
    int c0 = lane * 2;
    int head = c0 / F;
    float ad_d = __ldg(&g_ad[(size_t)n * H + head]);
    const __nv_bfloat162* hb2 = (const __nv_bfloat162*)g_hb;

    float den = __expf(lrelu(__ldg(&g_as[(size_t)n * H + head]) + ad_d));
    float2 hv = __bfloat1622float2(hb2[(size_t)n * 32 + lane]);
    float a0 = den * hv.x, a1 = den * hv.y;

    int beg = g_off[n], end = g_off[n + 1];
    int j = beg;
    for (; j + 8 <= end; j += 8) {
        int s[8]; float w[8]; float2 p[8];
#pragma unroll
        for (int q = 0; q < 8; q++) s[q] = __ldg(&g_adj[j + q]);
#pragma unroll
        for (int q = 0; q < 8; q++)
            w[q] = __expf(lrelu(__ldg(&g_as[(size_t)s[q] * H + head]) + ad_d));
#pragma unroll
        for (int q = 0; q < 8; q++)
            p[q] = __bfloat1622float2(hb2[(size_t)s[q] * 32 + lane]);
#pragma unroll
        for (int q = 0; q < 8; q++) {
            den += w[q];
            a0 += w[q] * p[q].x;
            a1 += w[q] * p[q].y;
        }
    }
    for (; j + 4 <= end; j += 4) {
        int s[4]; float w[4]; float2 p[4];
#pragma unroll
        for (int q = 0; q < 4; q++) s[q] = __ldg(&g_adj[j + q]);
#pragma unroll
        for (int q = 0; q < 4; q++)
            w[q] = __expf(lrelu(__ldg(&g_as[(size_t)s[q] * H + head]) + ad_d));
#pragma unroll
        for (int q = 0; q < 4; q++)
            p[q] = __bfloat1622float2(hb2[(size_t)s[q] * 32 + lane]);
#pragma unroll
        for (int q = 0; q < 4; q++) {
            den += w[q];
            a0 += w[q] * p[q].x;
            a1 += w[q] * p[q].y;
        }
    }
    for (; j < end; j++) {
        int s = __ldg(&g_adj[j]);
        float w = __expf(lrelu(__ldg(&g_as[(size_t)s * H + head]) + ad_d));
        float2 p = __bfloat1622float2(hb2[(size_t)s * 32 + lane]);
        den += w; a0 += w * p.x; a1 += w * p.y;
    }
    float inv = 1.f / den;
    float o0 = eluf(a0 * inv + b[c0]);
    float o1 = eluf(a1 * inv + b[c0 + 1]);
    ((float2*)g_x)[(size_t)n * 32 + lane] = make_float2(o0, o1);
}

// ---------------- final scoring ----------------------------------------------
__global__ void k_score(const void* __restrict__ bu_, const void* __restrict__ bi_,
                        float* __restrict__ out) {
    int gid = blockIdx.x * blockDim.x + threadIdx.x;
    if (gid >= NB * 8) return;
    int p = gid >> 3, l = gid & 7;
    int u, it;
    if (g_is64) {
        u  = (int)((const long long*)bu_)[p];
        it = (int)((const long long*)bi_)[p];
    } else {
        u  = ((const int*)bu_)[p];
        it = ((const int*)bi_)[p];
    }
    const float* xu = &g_x[(long)u * 64];
    const float* xv = &g_x[((long)it + N_USERS) * 64];
    int o = l * 8;
    float acc = 0.f;
#pragma unroll
    for (int k = 0; k < 8; k++) acc += xu[o + k] * xv[o + k];
    acc += __shfl_xor_sync(0xffffffffu, acc, 1);
    acc += __shfl_xor_sync(0xffffffffu, acc, 2);
    acc += __shfl_xor_sync(0xffffffffu, acc, 4);
    if (l == 0) out[p] = 1.f / (1.f + expf(-acc));
}

// ---------------- host launcher ----------------------------------------------
extern "C" void kernel_launch(void* const* d_in, const int* in_sizes, int n_in,
                              void* d_out, int out_size) {
    const void *edge = nullptr, *bu = nullptr, *bi = nullptr;
    const float *ue = nullptr, *ie = nullptr, *W1 = nullptr, *W2 = nullptr;
    const float* v64[6] = {nullptr, nullptr, nullptr, nullptr, nullptr, nullptr};
    int c64 = 0;
    for (int i = 0; i < n_in; i++) {
        int sz = in_sizes[i];
        if      (sz == 2 * NE)        edge = d_in[i];
        else if (sz == NB)            { if (!bu) bu = d_in[i]; else bi = d_in[i]; }
        else if (sz == N_USERS * DD)  ue = (const float*)d_in[i];
        else if (sz == N_ITEMS * DD)  ie = (const float*)d_in[i];
        else if (sz == DD * DD)       { if (!W1) W1 = (const float*)d_in[i];
                                        else     W2 = (const float*)d_in[i]; }
        else if (sz == 64 && c64 < 6) v64[c64++] = (const float*)d_in[i];
    }
    const float *as1 = v64[0], *ad1 = v64[1], *b1 = v64[2];
    const float *as2 = v64[3], *ad2 = v64[4], *b2 = v64[5];

    const int TB = 256;
    const int EB = (NE + TB - 1) / TB;

    k_init   <<<(NN + TB - 1) / TB, TB>>>((const int*)edge);
    k_count  <<<EB, TB>>>(edge);
    k_s1     <<<SB, 256>>>();
    k_s2     <<<1, 1024>>>();
    k_s3     <<<SB, 256>>>();
    k_scatter<<<EB, TB>>>(edge);

    // ---- layer 1: H=4, F=16 ----
    k_gemm<true, 4, 16> <<<(NN + 31) / 32, 128>>>(W1, ue, ie, as1, ad1);
    k_agg <4, 16>       <<<(NN + 7) / 8, TB>>>(b1);

    // ---- layer 2: H=1, F=64 ----
    k_gemm<false, 1, 64><<<(NN + 31) / 32, 128>>>(W2, nullptr, nullptr, as2, ad2);
    k_agg <1, 64>       <<<(NN + 7) / 8, TB>>>(b2);

    k_score<<<(NB * 8 + TB - 1) / TB, TB>>>(bu, bi, (float*)d_out);
}

// round 6
// speedup vs baseline: 2.3597x; 1.1361x over previous
#include <cuda_runtime.h>
#include <cuda_bf16.h>

#define N_USERS 100000
#define N_ITEMS 50000
#define NN      150000
#define NE      2000000
#define DD      64
#define NB      16384
#define SB      586      // ceil(NN/256) scan blocks

// ---------------- scratch (device globals) ----------------------------------
__device__ float          g_x [NN*DD];    // layer outputs (fp32)
__device__ __nv_bfloat16  g_hb[NN*DD];    // h = x@W in bf16 (gather payload)
__device__ float g_as [NN*4];
__device__ float g_ad [NN*4];
__device__ int   g_adj[NE];
__device__ int   g_cnt[NN];
__device__ int   g_off[NN+1];
__device__ int   g_pos[NN];
__device__ int   g_spine[1024];
__device__ int   g_is64;

// ---------------- helpers ---------------------------------------------------
__device__ __forceinline__ float lrelu(float x) { return x > 0.f ? x : 0.2f * x; }
__device__ __forceinline__ float eluf (float v) { return v > 0.f ? v : expf(v) - 1.f; }

// ---------------- init: zero counters + dtype detect -------------------------
__global__ void k_init(const int* __restrict__ ei) {
    int i = blockIdx.x * blockDim.x + threadIdx.x;
    if (i < NN) g_cnt[i] = 0;
    if (blockIdx.x == 0 && threadIdx.x == 0) {
        int all0 = 1;
        for (int k = 0; k < 64; k++)
            if (ei[2 * k + 1] != 0) { all0 = 0; break; }
        g_is64 = all0;
    }
}

__global__ void k_count(const void* __restrict__ ei) {
    int e = blockIdx.x * blockDim.x + threadIdx.x;
    if (e >= NE) return;
    int d = g_is64 ? (int)((const long long*)ei)[NE + e]
                   : ((const int*)ei)[NE + e];
    atomicAdd(&g_cnt[d], 1);
}

__global__ void k_s1() {
    __shared__ int sm[256];
    int i = blockIdx.x * 256 + threadIdx.x;
    sm[threadIdx.x] = (i < NN) ? g_cnt[i] : 0;
    __syncthreads();
    for (int s = 128; s > 0; s >>= 1) {
        if (threadIdx.x < s) sm[threadIdx.x] += sm[threadIdx.x + s];
        __syncthreads();
    }
    if (threadIdx.x == 0) g_spine[blockIdx.x] = sm[0];
}

__global__ void k_s2() {
    __shared__ int sm[1024];
    int t = threadIdx.x;
    sm[t] = (t < SB) ? g_spine[t] : 0;
    __syncthreads();
    for (int d = 1; d < 1024; d <<= 1) {
        int v = (t >= d) ? sm[t - d] : 0;
        __syncthreads();
        sm[t] += v;
        __syncthreads();
    }
    g_spine[t] = (t == 0) ? 0 : sm[t - 1];
    if (t == 0) g_off[NN] = NE;
}

__global__ void k_s3() {
    __shared__ int sm[256];
    int t = threadIdx.x;
    int i = blockIdx.x * 256 + t;
    int v = (i < NN) ? g_cnt[i] : 0;
    sm[t] = v;
    __syncthreads();
    for (int d = 1; d < 256; d <<= 1) {
        int u = (t >= d) ? sm[t - d] : 0;
        __syncthreads();
        sm[t] += u;
        __syncthreads();
    }
    int excl = sm[t] - v + g_spine[blockIdx.x];
    if (i < NN) { g_off[i] = excl; g_pos[i] = excl; }
}

__global__ void k_scatter(const void* __restrict__ ei) {
    int e = blockIdx.x * blockDim.x + threadIdx.x;
    if (e >= NE) return;
    int s, d;
    if (g_is64) {
        const long long* p = (const long long*)ei;
        s = (int)p[e]; d = (int)p[NE + e];
    } else {
        const int* p = (const int*)ei;
        s = p[e]; d = p[NE + e];
    }
    int pos = atomicAdd(&g_pos[d], 1);
    g_adj[pos] = s;
}

// ---------------- fused GEMM + alpha ------------------------------------------
template <bool FIRST, int H, int F>
__global__ void k_gemm(const float* __restrict__ W,
                       const float* __restrict__ ue,
                       const float* __restrict__ ie,
                       const float* __restrict__ a_src,
                       const float* __restrict__ a_dst) {
    __shared__ float sW[64 * 64];
    __shared__ float sxT[64][32];
    int t = threadIdx.x;
#pragma unroll
    for (int i = 0; i < 8; i++)
        *(float4*)&sW[(t + 128 * i) * 4] = *(const float4*)&W[(t + 128 * i) * 4];
    int n0 = blockIdx.x * 32;
#pragma unroll
    for (int i = 0; i < 4; i++) {
        int f = t + 128 * i;
        int node = f >> 4;
        int col  = (f & 15) * 4;
        int n = n0 + node;
        float4 v = make_float4(0.f, 0.f, 0.f, 0.f);
        if (n < NN) {
            const float* row = FIRST
                ? (n < N_USERS ? ue + (size_t)n * 64
                               : ie + (size_t)(n - N_USERS) * 64)
                : g_x + (size_t)n * 64;
            v = *(const float4*)(row + col);
        }
        sxT[col + 0][node] = v.x; sxT[col + 1][node] = v.y;
        sxT[col + 2][node] = v.z; sxT[col + 3][node] = v.w;
    }
    __syncthreads();
    int ng = t >> 4;
    int cg = t & 15;
    float acc[4][4];
#pragma unroll
    for (int i = 0; i < 4; i++)
#pragma unroll
        for (int j = 0; j < 4; j++) acc[i][j] = 0.f;
#pragma unroll 8
    for (int k = 0; k < 64; k++) {
        float4 xv = *(float4*)&sxT[k][ng * 4];
        float4 wv = *(float4*)&sW[k * 64 + cg * 4];
        acc[0][0] += xv.x * wv.x; acc[0][1] += xv.x * wv.y;
        acc[0][2] += xv.x * wv.z; acc[0][3] += xv.x * wv.w;
        acc[1][0] += xv.y * wv.x; acc[1][1] += xv.y * wv.y;
        acc[1][2] += xv.y * wv.z; acc[1][3] += xv.y * wv.w;
        acc[2][0] += xv.z * wv.x; acc[2][1] += xv.z * wv.y;
        acc[2][2] += xv.z * wv.z; acc[2][3] += xv.z * wv.w;
        acc[3][0] += xv.w * wv.x; acc[3][1] += xv.w * wv.y;
        acc[3][2] += xv.w * wv.z; acc[3][3] += xv.w * wv.w;
    }
#pragma unroll
    for (int i = 0; i < 4; i++) {
        int n = n0 + ng * 4 + i;
        if (n < NN) {
            __nv_bfloat162 p0 = __float22bfloat162_rn(make_float2(acc[i][0], acc[i][1]));
            __nv_bfloat162 p1 = __float22bfloat162_rn(make_float2(acc[i][2], acc[i][3]));
            uint2 pk;
            pk.x = *(unsigned*)&p0;
            pk.y = *(unsigned*)&p1;
            *(uint2*)&g_hb[(size_t)n * 64 + cg * 4] = pk;
        }
    }
    float4 av = *(const float4*)&a_src[cg * 4];
    float4 dv = *(const float4*)&a_dst[cg * 4];
    float ps[4], pd[4];
#pragma unroll
    for (int i = 0; i < 4; i++) {
        ps[i] = acc[i][0]*av.x + acc[i][1]*av.y + acc[i][2]*av.z + acc[i][3]*av.w;
        pd[i] = acc[i][0]*dv.x + acc[i][1]*dv.y + acc[i][2]*dv.z + acc[i][3]*dv.w;
    }
    if (H == 4) {
#pragma unroll
        for (int i = 0; i < 4; i++) {
            ps[i] += __shfl_xor_sync(0xffffffffu, ps[i], 1);
            ps[i] += __shfl_xor_sync(0xffffffffu, ps[i], 2);
            pd[i] += __shfl_xor_sync(0xffffffffu, pd[i], 1);
            pd[i] += __shfl_xor_sync(0xffffffffu, pd[i], 2);
        }
        if ((cg & 3) == 0) {
            int head = cg >> 2;
#pragma unroll
            for (int i = 0; i < 4; i++) {
                int n = n0 + ng * 4 + i;
                if (n < NN) {
                    g_as[n * 4 + head] = ps[i];
                    g_ad[n * 4 + head] = pd[i];
                }
            }
        }
    } else {
#pragma unroll
        for (int i = 0; i < 4; i++) {
            ps[i] += __shfl_xor_sync(0xffffffffu, ps[i], 1);
            ps[i] += __shfl_xor_sync(0xffffffffu, ps[i], 2);
            ps[i] += __shfl_xor_sync(0xffffffffu, ps[i], 4);
            ps[i] += __shfl_xor_sync(0xffffffffu, ps[i], 8);
            pd[i] += __shfl_xor_sync(0xffffffffu, pd[i], 1);
            pd[i] += __shfl_xor_sync(0xffffffffu, pd[i], 2);
            pd[i] += __shfl_xor_sync(0xffffffffu, pd[i], 4);
            pd[i] += __shfl_xor_sync(0xffffffffu, pd[i], 8);
        }
        if (cg == 0) {
#pragma unroll
            for (int i = 0; i < 4; i++) {
                int n = n0 + ng * 4 + i;
                if (n < NN) { g_as[n] = ps[i]; g_ad[n] = pd[i]; }
            }
        }
    }
}

// ---------------- fused aggregation: TWO nodes per warp ----------------------
// Half-warp per node, lane owns 4 cols (one uint2 = 4 bf16). The two halves
// run independent degree loops (divergence = max(degA,degB)); every memory
// instruction carries two independent dependency chains -> 2x MLP.
template <int H, int F>
__global__ void k_agg(const float* __restrict__ b) {
    int lane = threadIdx.x & 31;
    int wrp  = threadIdx.x >> 5;
    int half = lane >> 4;
    int l    = lane & 15;
    int n    = blockIdx.x * 16 + wrp * 2 + half;   // NN % 16 == 0
    int c0   = l * 4;
    int head = c0 / F;

    float ad_d = __ldg(&g_ad[(size_t)n * H + head]);
    float den  = __expf(lrelu(__ldg(&g_as[(size_t)n * H + head]) + ad_d));
    const uint2* hb = (const uint2*)g_hb;          // row = 16 uint2 (64 bf16)
    uint2 hs = hb[(size_t)n * 16 + l];
    float2 h01 = __bfloat1622float2(*(__nv_bfloat162*)&hs.x);
    float2 h23 = __bfloat1622float2(*(__nv_bfloat162*)&hs.y);
    float a0 = den * h01.x, a1 = den * h01.y;
    float a2 = den * h23.x, a3 = den * h23.y;

    int beg = g_off[n], end = g_off[n + 1];
    int j = beg;
    for (; j + 8 <= end; j += 8) {
        int s[8]; float w[8]; uint2 p[8];
#pragma unroll
        for (int q = 0; q < 8; q++) s[q] = __ldg(&g_adj[j + q]);
#pragma unroll
        for (int q = 0; q < 8; q++)
            w[q] = __expf(lrelu(__ldg(&g_as[(size_t)s[q] * H + head]) + ad_d));
#pragma unroll
        for (int q = 0; q < 8; q++) p[q] = hb[(size_t)s[q] * 16 + l];
#pragma unroll
        for (int q = 0; q < 8; q++) {
            float2 q01 = __bfloat1622float2(*(__nv_bfloat162*)&p[q].x);
            float2 q23 = __bfloat1622float2(*(__nv_bfloat162*)&p[q].y);
            den += w[q];
            a0 += w[q] * q01.x; a1 += w[q] * q01.y;
            a2 += w[q] * q23.x; a3 += w[q] * q23.y;
        }
    }
    for (; j + 4 <= end; j += 4) {
        int s[4]; float w[4]; uint2 p[4];
#pragma unroll
        for (int q = 0; q < 4; q++) s[q] = __ldg(&g_adj[j + q]);
#pragma unroll
        for (int q = 0; q < 4; q++)
            w[q] = __expf(lrelu(__ldg(&g_as[(size_t)s[q] * H + head]) + ad_d));
#pragma unroll
        for (int q = 0; q < 4; q++) p[q] = hb[(size_t)s[q] * 16 + l];
#pragma unroll
        for (int q = 0; q < 4; q++) {
            float2 q01 = __bfloat1622float2(*(__nv_bfloat162*)&p[q].x);
            float2 q23 = __bfloat1622float2(*(__nv_bfloat162*)&p[q].y);
            den += w[q];
            a0 += w[q] * q01.x; a1 += w[q] * q01.y;
            a2 += w[q] * q23.x; a3 += w[q] * q23.y;
        }
    }
    for (; j < end; j++) {
        int s = __ldg(&g_adj[j]);
        float w = __expf(lrelu(__ldg(&g_as[(size_t)s * H + head]) + ad_d));
        uint2 p = hb[(size_t)s * 16 + l];
        float2 q01 = __bfloat1622float2(*(__nv_bfloat162*)&p.x);
        float2 q23 = __bfloat1622float2(*(__nv_bfloat162*)&p.y);
        den += w;
        a0 += w * q01.x; a1 += w * q01.y;
        a2 += w * q23.x; a3 += w * q23.y;
    }
    float inv = 1.f / den;
    float4 o;
    o.x = eluf(a0 * inv + b[c0 + 0]);
    o.y = eluf(a1 * inv + b[c0 + 1]);
    o.z = eluf(a2 * inv + b[c0 + 2]);
    o.w = eluf(a3 * inv + b[c0 + 3]);
    *(float4*)&g_x[(size_t)n * 64 + c0] = o;
}

// ---------------- final scoring ----------------------------------------------
__global__ void k_score(const void* __restrict__ bu_, const void* __restrict__ bi_,
                        float* __restrict__ out) {
    int gid = blockIdx.x * blockDim.x + threadIdx.x;
    if (gid >= NB * 8) return;
    int p = gid >> 3, l = gid & 7;
    int u, it;
    if (g_is64) {
        u  = (int)((const long long*)bu_)[p];
        it = (int)((const long long*)bi_)[p];
    } else {
        u  = ((const int*)bu_)[p];
        it = ((const int*)bi_)[p];
    }
    const float* xu = &g_x[(long)u * 64];
    const float* xv = &g_x[((long)it + N_USERS) * 64];
    int o = l * 8;
    float acc = 0.f;
#pragma unroll
    for (int k = 0; k < 8; k++) acc += xu[o + k] * xv[o + k];
    acc += __shfl_xor_sync(0xffffffffu, acc, 1);
    acc += __shfl_xor_sync(0xffffffffu, acc, 2);
    acc += __shfl_xor_sync(0xffffffffu, acc, 4);
    if (l == 0) out[p] = 1.f / (1.f + expf(-acc));
}

// ---------------- host launcher ----------------------------------------------
extern "C" void kernel_launch(void* const* d_in, const int* in_sizes, int n_in,
                              void* d_out, int out_size) {
    const void *edge = nullptr, *bu = nullptr, *bi = nullptr;
    const float *ue = nullptr, *ie = nullptr, *W1 = nullptr, *W2 = nullptr;
    const float* v64[6] = {nullptr, nullptr, nullptr, nullptr, nullptr, nullptr};
    int c64 = 0;
    for (int i = 0; i < n_in; i++) {
        int sz = in_sizes[i];
        if      (sz == 2 * NE)        edge = d_in[i];
        else if (sz == NB)            { if (!bu) bu = d_in[i]; else bi = d_in[i]; }
        else if (sz == N_USERS * DD)  ue = (const float*)d_in[i];
        else if (sz == N_ITEMS * DD)  ie = (const float*)d_in[i];
        else if (sz == DD * DD)       { if (!W1) W1 = (const float*)d_in[i];
                                        else     W2 = (const float*)d_in[i]; }
        else if (sz == 64 && c64 < 6) v64[c64++] = (const float*)d_in[i];
    }
    const float *as1 = v64[0], *ad1 = v64[1], *b1 = v64[2];
    const float *as2 = v64[3], *ad2 = v64[4], *b2 = v64[5];

    const int TB = 256;
    const int EB = (NE + TB - 1) / TB;

    k_init   <<<(NN + TB - 1) / TB, TB>>>((const int*)edge);
    k_count  <<<EB, TB>>>(edge);
    k_s1     <<<SB, 256>>>();
    k_s2     <<<1, 1024>>>();
    k_s3     <<<SB, 256>>>();
    k_scatter<<<EB, TB>>>(edge);

    // ---- layer 1: H=4, F=16 ----
    k_gemm<true, 4, 16> <<<(NN + 31) / 32, 128>>>(W1, ue, ie, as1, ad1);
    k_agg <4, 16>       <<<NN / 16, TB>>>(b1);

    // ---- layer 2: H=1, F=64 ----
    k_gemm<false, 1, 64><<<(NN + 31) / 32, 128>>>(W2, nullptr, nullptr, as2, ad2);
    k_agg <1, 64>       <<<NN / 16, TB>>>(b2);

    k_score<<<(NB * 8 + TB - 1) / TB, TB>>>(bu, bi, (float*)d_out);
}

// round 7
// speedup vs baseline: 2.6081x; 1.1053x over previous
#include <cuda_runtime.h>
#include <cuda_bf16.h>

#define N_USERS 100000
#define N_ITEMS 50000
#define NN      150000
#define NE      2000000
#define DD      64
#define NB      16384
#define SB      586      // ceil(NN/256) scan blocks

// ---------------- scratch (device globals) ----------------------------------
__device__ float          g_x [NN*DD];    // layer outputs (fp32)
__device__ __nv_bfloat16  g_hb[NN*DD];    // h = x@W in bf16 (gather payload)
__device__ float g_as [NN*4];
__device__ float g_ad [NN*4];
__device__ int   g_adj[NE];
__device__ int   g_cnt[NN];
__device__ int   g_off[NN+1];
__device__ int   g_pos[NN];
__device__ int   g_spine[1024];
__device__ int   g_is64;

// ---------------- helpers ---------------------------------------------------
__device__ __forceinline__ float lrelu(float x) { return x > 0.f ? x : 0.2f * x; }
__device__ __forceinline__ float eluf (float v) { return v > 0.f ? v : expf(v) - 1.f; }
__device__ __forceinline__ float2 bf2f(unsigned u) {
    return __bfloat1622float2(*(__nv_bfloat162*)&u);
}

// ---------------- init: zero counters + dtype detect -------------------------
__global__ void k_init(const int* __restrict__ ei) {
    int i = blockIdx.x * blockDim.x + threadIdx.x;
    if (i < NN) g_cnt[i] = 0;
    if (blockIdx.x == 0 && threadIdx.x == 0) {
        int all0 = 1;
        for (int k = 0; k < 64; k++)
            if (ei[2 * k + 1] != 0) { all0 = 0; break; }
        g_is64 = all0;
    }
}

__global__ void k_count(const void* __restrict__ ei) {
    int e = blockIdx.x * blockDim.x + threadIdx.x;
    if (e >= NE) return;
    int d = g_is64 ? (int)((const long long*)ei)[NE + e]
                   : ((const int*)ei)[NE + e];
    atomicAdd(&g_cnt[d], 1);
}

// block sums -> spine (shuffle reduce)
__global__ void k_s1() {
    __shared__ int ws[8];
    int t = threadIdx.x;
    int i = blockIdx.x * 256 + t;
    int v = (i < NN) ? g_cnt[i] : 0;
#pragma unroll
    for (int d = 16; d; d >>= 1) v += __shfl_xor_sync(0xffffffffu, v, d);
    if ((t & 31) == 0) ws[t >> 5] = v;
    __syncthreads();
    if (t < 8) {
        int s = ws[t];
#pragma unroll
        for (int d = 4; d; d >>= 1) s += __shfl_xor_sync(0xffu, s, d);
        if (t == 0) g_spine[blockIdx.x] = s;
    }
}

// exclusive scan of spine (shuffle-based, 1024 threads)
__global__ void k_s2() {
    __shared__ int ws[32];
    int t = threadIdx.x;
    int orig = (t < SB) ? g_spine[t] : 0;
    int v = orig;
#pragma unroll
    for (int d = 1; d < 32; d <<= 1) {
        int u = __shfl_up_sync(0xffffffffu, v, d);
        if ((t & 31) >= d) v += u;
    }
    if ((t & 31) == 31) ws[t >> 5] = v;
    __syncthreads();
    if (t < 32) {
        int s = ws[t];
#pragma unroll
        for (int d = 1; d < 32; d <<= 1) {
            int u = __shfl_up_sync(0xffffffffu, s, d);
            if (t >= d) s += u;
        }
        ws[t] = s;
    }
    __syncthreads();
    int incl = v + ((t >= 32) ? ws[(t >> 5) - 1] : 0);
    if (t < SB) g_spine[t] = incl - orig;
    if (t == 0) g_off[NN] = NE;
}

// per-block exclusive scan + spine offset (shuffle-based)
__global__ void k_s3() {
    __shared__ int ws[8];
    int t = threadIdx.x;
    int i = blockIdx.x * 256 + t;
    int orig = (i < NN) ? g_cnt[i] : 0;
    int v = orig;
#pragma unroll
    for (int d = 1; d < 32; d <<= 1) {
        int u = __shfl_up_sync(0xffffffffu, v, d);
        if ((t & 31) >= d) v += u;
    }
    if ((t & 31) == 31) ws[t >> 5] = v;
    __syncthreads();
    if (t < 8) {
        int s = ws[t];
#pragma unroll
        for (int d = 1; d < 8; d <<= 1) {
            int u = __shfl_up_sync(0xffu, s, d);
            if (t >= d) s += u;
        }
        ws[t] = s;
    }
    __syncthreads();
    int incl = v + ((t >= 32) ? ws[(t >> 5) - 1] : 0);
    int excl = incl - orig + g_spine[blockIdx.x];
    if (i < NN) { g_off[i] = excl; g_pos[i] = excl; }
}

__global__ void k_scatter(const void* __restrict__ ei) {
    int e = blockIdx.x * blockDim.x + threadIdx.x;
    if (e >= NE) return;
    int s, d;
    if (g_is64) {
        const long long* p = (const long long*)ei;
        s = (int)p[e]; d = (int)p[NE + e];
    } else {
        const int* p = (const int*)ei;
        s = p[e]; d = p[NE + e];
    }
    int pos = atomicAdd(&g_pos[d], 1);
    g_adj[pos] = s;
}

// ---------------- fused GEMM + alpha ------------------------------------------
// 128 threads, 64 nodes/block; thread = 4 nodes x 8 cols (32 FFMA / 3 LDS.128).
template <bool FIRST, int H>
__global__ void k_gemm(const float* __restrict__ W,
                       const float* __restrict__ ue,
                       const float* __restrict__ ie,
                       const float* __restrict__ a_src,
                       const float* __restrict__ a_dst) {
    __shared__ float sW[64 * 64];
    __shared__ float sxT[64][68];
    int t = threadIdx.x;
#pragma unroll
    for (int i = 0; i < 8; i++)
        *(float4*)&sW[(t + 128 * i) * 4] = *(const float4*)&W[(t + 128 * i) * 4];
    int n0 = blockIdx.x * 64;
#pragma unroll
    for (int i = 0; i < 8; i++) {
        int f = t + 128 * i;           // float4 slot 0..1023
        int node = f >> 4;             // 0..63
        int col  = (f & 15) * 4;
        int n = n0 + node;
        float4 v = make_float4(0.f, 0.f, 0.f, 0.f);
        if (n < NN) {
            const float* row = FIRST
                ? (n < N_USERS ? ue + (size_t)n * 64
                               : ie + (size_t)(n - N_USERS) * 64)
                : g_x + (size_t)n * 64;
            v = *(const float4*)(row + col);
        }
        sxT[col + 0][node] = v.x; sxT[col + 1][node] = v.y;
        sxT[col + 2][node] = v.z; sxT[col + 3][node] = v.w;
    }
    __syncthreads();
    int ng = t >> 3;      // 0..15 (4 nodes each)
    int cg = t & 7;       // 0..7  (8 cols each)
    float acc[4][8];
#pragma unroll
    for (int i = 0; i < 4; i++)
#pragma unroll
        for (int j = 0; j < 8; j++) acc[i][j] = 0.f;
#pragma unroll 4
    for (int k = 0; k < 64; k++) {
        float4 xv = *(float4*)&sxT[k][ng * 4];
        float4 w0 = *(float4*)&sW[k * 64 + cg * 8];
        float4 w1 = *(float4*)&sW[k * 64 + cg * 8 + 4];
        float xi;
#pragma unroll
        for (int i = 0; i < 4; i++) {
            xi = (i == 0) ? xv.x : (i == 1) ? xv.y : (i == 2) ? xv.z : xv.w;
            acc[i][0] += xi * w0.x; acc[i][1] += xi * w0.y;
            acc[i][2] += xi * w0.z; acc[i][3] += xi * w0.w;
            acc[i][4] += xi * w1.x; acc[i][5] += xi * w1.y;
            acc[i][6] += xi * w1.z; acc[i][7] += xi * w1.w;
        }
    }
    // write h in bf16 (uint4 = 8 bf16)
#pragma unroll
    for (int i = 0; i < 4; i++) {
        int n = n0 + ng * 4 + i;
        if (n < NN) {
            __nv_bfloat162 b0 = __float22bfloat162_rn(make_float2(acc[i][0], acc[i][1]));
            __nv_bfloat162 b1 = __float22bfloat162_rn(make_float2(acc[i][2], acc[i][3]));
            __nv_bfloat162 b2 = __float22bfloat162_rn(make_float2(acc[i][4], acc[i][5]));
            __nv_bfloat162 b3 = __float22bfloat162_rn(make_float2(acc[i][6], acc[i][7]));
            uint4 pk;
            pk.x = *(unsigned*)&b0; pk.y = *(unsigned*)&b1;
            pk.z = *(unsigned*)&b2; pk.w = *(unsigned*)&b3;
            *(uint4*)&g_hb[(size_t)n * 64 + cg * 8] = pk;
        }
    }
    // fused alpha: per-thread partial dot over its 8 cols (a vectors indexed by
    // global column: layout [H,F] flattened = 64)
    float4 av0 = *(const float4*)&a_src[cg * 8];
    float4 av1 = *(const float4*)&a_src[cg * 8 + 4];
    float4 dv0 = *(const float4*)&a_dst[cg * 8];
    float4 dv1 = *(const float4*)&a_dst[cg * 8 + 4];
    float ps[4], pd[4];
#pragma unroll
    for (int i = 0; i < 4; i++) {
        ps[i] = acc[i][0]*av0.x + acc[i][1]*av0.y + acc[i][2]*av0.z + acc[i][3]*av0.w
              + acc[i][4]*av1.x + acc[i][5]*av1.y + acc[i][6]*av1.z + acc[i][7]*av1.w;
        pd[i] = acc[i][0]*dv0.x + acc[i][1]*dv0.y + acc[i][2]*dv0.z + acc[i][3]*dv0.w
              + acc[i][4]*dv1.x + acc[i][5]*dv1.y + acc[i][6]*dv1.z + acc[i][7]*dv1.w;
    }
    if (H == 4) {
        // head = cg>>1 ; reduce cg pairs
#pragma unroll
        for (int i = 0; i < 4; i++) {
            ps[i] += __shfl_xor_sync(0xffffffffu, ps[i], 1);
            pd[i] += __shfl_xor_sync(0xffffffffu, pd[i], 1);
        }
        if ((cg & 1) == 0) {
            int head = cg >> 1;
#pragma unroll
            for (int i = 0; i < 4; i++) {
                int n = n0 + ng * 4 + i;
                if (n < NN) {
                    g_as[n * 4 + head] = ps[i];
                    g_ad[n * 4 + head] = pd[i];
                }
            }
        }
    } else {
#pragma unroll
        for (int i = 0; i < 4; i++) {
            ps[i] += __shfl_xor_sync(0xffffffffu, ps[i], 1);
            ps[i] += __shfl_xor_sync(0xffffffffu, ps[i], 2);
            ps[i] += __shfl_xor_sync(0xffffffffu, ps[i], 4);
            pd[i] += __shfl_xor_sync(0xffffffffu, pd[i], 1);
            pd[i] += __shfl_xor_sync(0xffffffffu, pd[i], 2);
            pd[i] += __shfl_xor_sync(0xffffffffu, pd[i], 4);
        }
        if (cg == 0) {
#pragma unroll
            for (int i = 0; i < 4; i++) {
                int n = n0 + ng * 4 + i;
                if (n < NN) { g_as[n] = ps[i]; g_ad[n] = pd[i]; }
            }
        }
    }
}

// ---------------- fused aggregation: FOUR nodes per warp ---------------------
// Quarter-warp per node, lane owns 8 cols (one uint4 = 8 bf16; row gather is
// still one 128B wavefront). 4 independent chains/warp -> 4x MLP.
template <int H, int F>
__global__ void k_agg(const float* __restrict__ b) {
    int lane = threadIdx.x & 31;
    int wrp  = threadIdx.x >> 5;
    int quad = lane >> 3;
    int l    = lane & 7;
    int n    = blockIdx.x * 32 + wrp * 4 + quad;
    if (n >= NN) return;
    int c0   = l * 8;
    int head = c0 / F;

    float ad_d = __ldg(&g_ad[(size_t)n * H + head]);
    float den  = __expf(lrelu(__ldg(&g_as[(size_t)n * H + head]) + ad_d));
    const uint4* hb = (const uint4*)g_hb;          // row = 8 uint4 (64 bf16)
    uint4 hs = hb[(size_t)n * 8 + l];
    float2 h01 = bf2f(hs.x), h23 = bf2f(hs.y), h45 = bf2f(hs.z), h67 = bf2f(hs.w);
    float a0 = den * h01.x, a1 = den * h01.y, a2 = den * h23.x, a3 = den * h23.y;
    float a4 = den * h45.x, a5 = den * h45.y, a6 = den * h67.x, a7 = den * h67.y;

    int beg = g_off[n], end = g_off[n + 1];
    int j = beg;
    for (; j + 4 <= end; j += 4) {
        int s[4]; float w[4]; uint4 p[4];
#pragma unroll
        for (int q = 0; q < 4; q++) s[q] = __ldg(&g_adj[j + q]);
#pragma unroll
        for (int q = 0; q < 4; q++)
            w[q] = __expf(lrelu(__ldg(&g_as[(size_t)s[q] * H + head]) + ad_d));
#pragma unroll
        for (int q = 0; q < 4; q++) p[q] = hb[(size_t)s[q] * 8 + l];
#pragma unroll
        for (int q = 0; q < 4; q++) {
            float2 q01 = bf2f(p[q].x), q23 = bf2f(p[q].y);
            float2 q45 = bf2f(p[q].z), q67 = bf2f(p[q].w);
            den += w[q];
            a0 += w[q] * q01.x; a1 += w[q] * q01.y;
            a2 += w[q] * q23.x; a3 += w[q] * q23.y;
            a4 += w[q] * q45.x; a5 += w[q] * q45.y;
            a6 += w[q] * q67.x; a7 += w[q] * q67.y;
        }
    }
    for (; j < end; j++) {
        int s = __ldg(&g_adj[j]);
        float w = __expf(lrelu(__ldg(&g_as[(size_t)s * H + head]) + ad_d));
        uint4 p = hb[(size_t)s * 8 + l];
        float2 q01 = bf2f(p.x), q23 = bf2f(p.y), q45 = bf2f(p.z), q67 = bf2f(p.w);
        den += w;
        a0 += w * q01.x; a1 += w * q01.y; a2 += w * q23.x; a3 += w * q23.y;
        a4 += w * q45.x; a5 += w * q45.y; a6 += w * q67.x; a7 += w * q67.y;
    }
    float inv = 1.f / den;
    float4 o0, o1;
    o0.x = eluf(a0 * inv + b[c0 + 0]);
    o0.y = eluf(a1 * inv + b[c0 + 1]);
    o0.z = eluf(a2 * inv + b[c0 + 2]);
    o0.w = eluf(a3 * inv + b[c0 + 3]);
    o1.x = eluf(a4 * inv + b[c0 + 4]);
    o1.y = eluf(a5 * inv + b[c0 + 5]);
    o1.z = eluf(a6 * inv + b[c0 + 6]);
    o1.w = eluf(a7 * inv + b[c0 + 7]);
    *(float4*)&g_x[(size_t)n * 64 + c0]     = o0;
    *(float4*)&g_x[(size_t)n * 64 + c0 + 4] = o1;
}

// ---------------- final scoring ----------------------------------------------
__global__ void k_score(const void* __restrict__ bu_, const void* __restrict__ bi_,
                        float* __restrict__ out) {
    int gid = blockIdx.x * blockDim.x + threadIdx.x;
    if (gid >= NB * 8) return;
    int p = gid >> 3, l = gid & 7;
    int u, it;
    if (g_is64) {
        u  = (int)((const long long*)bu_)[p];
        it = (int)((const long long*)bi_)[p];
    } else {
        u  = ((const int*)bu_)[p];
        it = ((const int*)bi_)[p];
    }
    const float* xu = &g_x[(long)u * 64];
    const float* xv = &g_x[((long)it + N_USERS) * 64];
    int o = l * 8;
    float acc = 0.f;
#pragma unroll
    for (int k = 0; k < 8; k++) acc += xu[o + k] * xv[o + k];
    acc += __shfl_xor_sync(0xffffffffu, acc, 1);
    acc += __shfl_xor_sync(0xffffffffu, acc, 2);
    acc += __shfl_xor_sync(0xffffffffu, acc, 4);
    if (l == 0) out[p] = 1.f / (1.f + expf(-acc));
}

// ---------------- host launcher ----------------------------------------------
extern "C" void kernel_launch(void* const* d_in, const int* in_sizes, int n_in,
                              void* d_out, int out_size) {
    const void *edge = nullptr, *bu = nullptr, *bi = nullptr;
    const float *ue = nullptr, *ie = nullptr, *W1 = nullptr, *W2 = nullptr;
    const float* v64[6] = {nullptr, nullptr, nullptr, nullptr, nullptr, nullptr};
    int c64 = 0;
    for (int i = 0; i < n_in; i++) {
        int sz = in_sizes[i];
        if      (sz == 2 * NE)        edge = d_in[i];
        else if (sz == NB)            { if (!bu) bu = d_in[i]; else bi = d_in[i]; }
        else if (sz == N_USERS * DD)  ue = (const float*)d_in[i];
        else if (sz == N_ITEMS * DD)  ie = (const float*)d_in[i];
        else if (sz == DD * DD)       { if (!W1) W1 = (const float*)d_in[i];
                                        else     W2 = (const float*)d_in[i]; }
        else if (sz == 64 && c64 < 6) v64[c64++] = (const float*)d_in[i];
    }
    const float *as1 = v64[0], *ad1 = v64[1], *b1 = v64[2];
    const float *as2 = v64[3], *ad2 = v64[4], *b2 = v64[5];

    const int TB = 256;
    const int EB = (NE + TB - 1) / TB;

    k_init   <<<(NN + TB - 1) / TB, TB>>>((const int*)edge);
    k_count  <<<EB, TB>>>(edge);
    k_s1     <<<SB, 256>>>();
    k_s2     <<<1, 1024>>>();
    k_s3     <<<SB, 256>>>();
    k_scatter<<<EB, TB>>>(edge);

    // ---- layer 1: H=4, F=16 ----
    k_gemm<true, 4> <<<(NN + 63) / 64, 128>>>(W1, ue, ie, as1, ad1);
    k_agg <4, 16>   <<<(NN + 31) / 32, TB>>>(b1);

    // ---- layer 2: H=1, F=64 ----
    k_gemm<false, 1><<<(NN + 63) / 64, 128>>>(W2, nullptr, nullptr, as2, ad2);
    k_agg <1, 64>   <<<(NN + 31) / 32, TB>>>(b2);

    k_score<<<(NB * 8 + TB - 1) / TB, TB>>>(bu, bi, (float*)d_out);
}